// round 3
// baseline (speedup 1.0000x reference)
#include <cuda_runtime.h>
#include <math.h>

// Problem constants (fixed by the dataset)
#define NN 8192
#define DD 512
#define EPSF 1e-8f

// Scratch (allocation-free: __device__ globals)
__device__ float g_Wh[(size_t)NN * DD];          // 16.8 MB
__device__ float g_norm[NN];
__device__ float g_S[(size_t)NN * NN];           // 268 MB

#define BM 128
#define BN 128
#define BK 16

// ---------------------------------------------------------------------------
// C = A @ B^T  (A: [M,K] row-major, B: [Ncols,K] row-major, C: [M,Ncols])
// If SIM: epilogue computes cosine sim + adjacency mask and writes sim_masked.
// Requires M,Ncols multiples of 128, K multiple of 16.
// ---------------------------------------------------------------------------
template <bool SIM>
__global__ __launch_bounds__(256, 2)
void gemm_nt(const float* __restrict__ A, const float* __restrict__ B,
             float* __restrict__ C, int M, int Ncols, int K,
             const int* __restrict__ adj, const float* __restrict__ norms)
{
    __shared__ float As[BK][BM];
    __shared__ float Bs[BK][BN];

    const int tid = threadIdx.x;          // 256 threads
    const int tx = tid & 15;              // 16 col-groups
    const int ty = tid >> 4;              // 16 row-groups
    const int rowBase = blockIdx.y * BM;
    const int colBase = blockIdx.x * BN;

    float acc[8][8];
#pragma unroll
    for (int i = 0; i < 8; i++)
#pragma unroll
        for (int j = 0; j < 8; j++) acc[i][j] = 0.f;

    for (int k0 = 0; k0 < K; k0 += BK) {
        // Load A tile (BM x BK) and B tile (BN x BK), both K-contiguous.
        // 128*16 = 2048 floats = 512 float4 each; 2 float4 per thread.
#pragma unroll
        for (int l = 0; l < 2; l++) {
            int idx = tid + l * 256;          // 0..511
            int r   = idx >> 2;               // 0..127
            int c4  = (idx & 3) << 2;         // 0,4,8,12
            float4 va = *reinterpret_cast<const float4*>(
                A + (size_t)(rowBase + r) * K + k0 + c4);
            As[c4 + 0][r] = va.x; As[c4 + 1][r] = va.y;
            As[c4 + 2][r] = va.z; As[c4 + 3][r] = va.w;
            float4 vb = *reinterpret_cast<const float4*>(
                B + (size_t)(colBase + r) * K + k0 + c4);
            Bs[c4 + 0][r] = vb.x; Bs[c4 + 1][r] = vb.y;
            Bs[c4 + 2][r] = vb.z; Bs[c4 + 3][r] = vb.w;
        }
        __syncthreads();

#pragma unroll
        for (int k = 0; k < BK; k++) {
            float a[8], b[8];
#pragma unroll
            for (int i = 0; i < 8; i++) a[i] = As[k][ty * 8 + i];
#pragma unroll
            for (int j = 0; j < 8; j++) b[j] = Bs[k][tx * 8 + j];
#pragma unroll
            for (int i = 0; i < 8; i++)
#pragma unroll
                for (int j = 0; j < 8; j++)
                    acc[i][j] = fmaf(a[i], b[j], acc[i][j]);
        }
        __syncthreads();
    }

    if (!SIM) {
#pragma unroll
        for (int i = 0; i < 8; i++) {
            int row = rowBase + ty * 8 + i;
#pragma unroll
            for (int j = 0; j < 8; j += 4) {
                int col = colBase + tx * 8 + j;
                float4 v = make_float4(acc[i][j], acc[i][j + 1],
                                       acc[i][j + 2], acc[i][j + 3]);
                *reinterpret_cast<float4*>(C + (size_t)row * Ncols + col) = v;
            }
        }
    } else {
        const float NEG_INF = __int_as_float(0xff800000);
        float ncv[8];
#pragma unroll
        for (int j = 0; j < 8; j++) ncv[j] = norms[colBase + tx * 8 + j];
#pragma unroll
        for (int i = 0; i < 8; i++) {
            int row = rowBase + ty * 8 + i;
            float nr = norms[row];
#pragma unroll
            for (int j = 0; j < 8; j += 4) {
                int col = colBase + tx * 8 + j;
                int4 a4 = *reinterpret_cast<const int4*>(
                    adj + (size_t)row * Ncols + col);
                float4 v;
                v.x = (a4.x > 0 || row == col + 0) ? acc[i][j + 0] / (nr * ncv[j + 0] + EPSF) : NEG_INF;
                v.y = (a4.y > 0 || row == col + 1) ? acc[i][j + 1] / (nr * ncv[j + 1] + EPSF) : NEG_INF;
                v.z = (a4.z > 0 || row == col + 2) ? acc[i][j + 2] / (nr * ncv[j + 2] + EPSF) : NEG_INF;
                v.w = (a4.w > 0 || row == col + 3) ? acc[i][j + 3] / (nr * ncv[j + 3] + EPSF) : NEG_INF;
                *reinterpret_cast<float4*>(C + (size_t)row * Ncols + col) = v;
            }
        }
    }
}

// ---------------------------------------------------------------------------
// C = A @ B  (A: [M,K] row-major, B: [K,Ncols] row-major)
// ---------------------------------------------------------------------------
__global__ __launch_bounds__(256, 2)
void gemm_nn(const float* __restrict__ A, const float* __restrict__ B,
             float* __restrict__ C, int M, int Ncols, int K)
{
    __shared__ float As[BK][BM];
    __shared__ float Bs[BK][BN];

    const int tid = threadIdx.x;
    const int tx = tid & 15;
    const int ty = tid >> 4;
    const int rowBase = blockIdx.y * BM;
    const int colBase = blockIdx.x * BN;

    float acc[8][8];
#pragma unroll
    for (int i = 0; i < 8; i++)
#pragma unroll
        for (int j = 0; j < 8; j++) acc[i][j] = 0.f;

    for (int k0 = 0; k0 < K; k0 += BK) {
#pragma unroll
        for (int l = 0; l < 2; l++) {
            int idx = tid + l * 256;          // 0..511
            // A tile: BM rows x BK cols (K contiguous) -> transpose into As
            int r   = idx >> 2;
            int c4  = (idx & 3) << 2;
            float4 va = *reinterpret_cast<const float4*>(
                A + (size_t)(rowBase + r) * K + k0 + c4);
            As[c4 + 0][r] = va.x; As[c4 + 1][r] = va.y;
            As[c4 + 2][r] = va.z; As[c4 + 3][r] = va.w;
            // B tile: BK rows x BN cols (N contiguous) -> direct
            int br = idx >> 5;                // 0..15
            int bc = (idx & 31) << 2;         // 0..124
            float4 vb = *reinterpret_cast<const float4*>(
                B + (size_t)(k0 + br) * Ncols + colBase + bc);
            *reinterpret_cast<float4*>(&Bs[br][bc]) = vb;
        }
        __syncthreads();

#pragma unroll
        for (int k = 0; k < BK; k++) {
            float a[8], b[8];
#pragma unroll
            for (int i = 0; i < 8; i++) a[i] = As[k][ty * 8 + i];
#pragma unroll
            for (int j = 0; j < 8; j++) b[j] = Bs[k][tx * 8 + j];
#pragma unroll
            for (int i = 0; i < 8; i++)
#pragma unroll
                for (int j = 0; j < 8; j++)
                    acc[i][j] = fmaf(a[i], b[j], acc[i][j]);
        }
        __syncthreads();
    }

#pragma unroll
    for (int i = 0; i < 8; i++) {
        int row = rowBase + ty * 8 + i;
#pragma unroll
        for (int j = 0; j < 8; j += 4) {
            int col = colBase + tx * 8 + j;
            float4 v = make_float4(acc[i][j], acc[i][j + 1],
                                   acc[i][j + 2], acc[i][j + 3]);
            *reinterpret_cast<float4*>(C + (size_t)row * Ncols + col) = v;
        }
    }
}

// ---------------------------------------------------------------------------
// Row L2 norms of Wh: one warp per row.
// ---------------------------------------------------------------------------
__global__ void row_norms(const float* __restrict__ Wh, float* __restrict__ nrm)
{
    int gw   = (blockIdx.x * blockDim.x + threadIdx.x) >> 5;
    int lane = threadIdx.x & 31;
    if (gw >= NN) return;
    const float* r = Wh + (size_t)gw * DD;
    float s = 0.f;
    for (int c = lane; c < DD; c += 32) { float v = r[c]; s = fmaf(v, v, s); }
#pragma unroll
    for (int off = 16; off > 0; off >>= 1)
        s += __shfl_xor_sync(0xffffffffu, s, off);
    if (lane == 0) nrm[gw] = sqrtf(s);
}

// ---------------------------------------------------------------------------
// Row softmax over S (in place). Diagonal guarantees a finite max, and
// expf(-inf - m) = 0, so -inf entries vanish cleanly.
// ---------------------------------------------------------------------------
__global__ void row_softmax(float* __restrict__ S)
{
    __shared__ float red[256];
    const size_t row = blockIdx.x;
    float* x = S + row * (size_t)NN;
    const int tid = threadIdx.x;

    float m = -1e30f;
    for (int c = tid; c < NN; c += 256) m = fmaxf(m, x[c]);
    red[tid] = m; __syncthreads();
    for (int s = 128; s > 0; s >>= 1) {
        if (tid < s) red[tid] = fmaxf(red[tid], red[tid + s]);
        __syncthreads();
    }
    m = red[0];
    __syncthreads();

    float sum = 0.f;
    for (int c = tid; c < NN; c += 256) sum += __expf(x[c] - m);
    red[tid] = sum; __syncthreads();
    for (int s = 128; s > 0; s >>= 1) {
        if (tid < s) red[tid] += red[tid + s];
        __syncthreads();
    }
    float inv = 1.0f / red[0];

    for (int c = tid; c < NN; c += 256) x[c] = __expf(x[c] - m) * inv;
}

// ---------------------------------------------------------------------------
extern "C" void kernel_launch(void* const* d_in, const int* in_sizes, int n_in,
                              void* d_out, int out_size)
{
    const float* h   = (const float*)d_in[0];   // [8192, 512]
    const int*   adj = (const int*)d_in[1];     // [8192, 8192]
    const float* W   = (const float*)d_in[2];   // [512, 512]
    float* out = (float*)d_out;                 // [8192, 512]

    void* p;
    cudaGetSymbolAddress(&p, g_Wh);   float* Wh  = (float*)p;
    cudaGetSymbolAddress(&p, g_norm); float* nrm = (float*)p;
    cudaGetSymbolAddress(&p, g_S);    float* S   = (float*)p;

    // 1) Wh = h @ W^T   [8192 x 512]
    gemm_nt<false><<<dim3(DD / BN, NN / BM), 256>>>(h, W, Wh, NN, DD, DD,
                                                    nullptr, nullptr);
    // 2) row norms of Wh
    row_norms<<<(NN * 32) / 256, 256>>>(Wh, nrm);
    // 3) S = masked cosine sim  [8192 x 8192]
    gemm_nt<true><<<dim3(NN / BN, NN / BM), 256>>>(Wh, Wh, S, NN, NN, DD,
                                                   adj, nrm);
    // 4) row softmax in place -> alpha
    row_softmax<<<NN, 256>>>(S);
    // 5) out = alpha @ Wh
    gemm_nn<<<dim3(DD / BN, NN / BM), 256>>>(S, Wh, out, NN, DD, NN);
}

// round 6
// speedup vs baseline: 2.5259x; 2.5259x over previous
#include <cuda_runtime.h>
#include <cuda_bf16.h>
#include <math.h>
#include <stdint.h>

#define NN 8192
#define DD 512
#define EPSF 1e-8f

// ---------------- scratch (__device__ globals; no allocation) ----------------
__device__ float g_Wh[(size_t)NN * DD];                 // 16.8 MB
__device__ float g_S [(size_t)NN * NN];                 // 268 MB
__device__ __nv_bfloat16 g_An_hi[(size_t)NN * DD];      // normalized Wh splits
__device__ __nv_bfloat16 g_An_lo[(size_t)NN * DD];
__device__ __nv_bfloat16 g_Bt_hi[(size_t)DD * NN];      // Wh^T splits
__device__ __nv_bfloat16 g_Bt_lo[(size_t)DD * NN];
__device__ __nv_bfloat16 g_a_hi [(size_t)NN * NN];      // alpha splits
__device__ __nv_bfloat16 g_a_lo [(size_t)NN * NN];

// ---------------- PTX helpers (all baseline PTX, sm_80+) --------------------
__device__ __forceinline__ uint32_t smem_u32(const void* p) {
    uint32_t a;
    asm("{ .reg .u64 t; cvta.to.shared.u64 t, %1; cvt.u32.u64 %0, t; }"
        : "=r"(a) : "l"(p));
    return a;
}
__device__ __forceinline__ void cpasync16(uint32_t dst, const void* src) {
    asm volatile("cp.async.cg.shared.global [%0], [%1], 16;"
                 :: "r"(dst), "l"(src) : "memory");
}
__device__ __forceinline__ void cp_commit() {
    asm volatile("cp.async.commit_group;" ::: "memory");
}
__device__ __forceinline__ void ldsm4(uint32_t* r, uint32_t addr) {
    asm volatile("ldmatrix.sync.aligned.m8n8.x4.shared.b16 {%0,%1,%2,%3}, [%4];"
                 : "=r"(r[0]), "=r"(r[1]), "=r"(r[2]), "=r"(r[3]) : "r"(addr));
}
__device__ __forceinline__ void mma16816(float* d, const uint32_t* a, const uint32_t* b) {
    asm volatile(
        "mma.sync.aligned.m16n8k16.row.col.f32.bf16.bf16.f32 "
        "{%0,%1,%2,%3}, {%4,%5,%6,%7}, {%8,%9}, {%0,%1,%2,%3};"
        : "+f"(d[0]), "+f"(d[1]), "+f"(d[2]), "+f"(d[3])
        : "r"(a[0]), "r"(a[1]), "r"(a[2]), "r"(a[3]), "r"(b[0]), "r"(b[1]));
}

// swizzled smem offset within a [128 rows x 32 bf16] tile (64B pitch, 16B units)
__device__ __forceinline__ uint32_t swz_off(int row, int u) {
    return (uint32_t)(row * 64 + ((u ^ ((row >> 1) & 3)) << 4));
}

// ---------------------------------------------------------------------------
// HMMA split-bf16 GEMM: C[M x N] = (Ahi+Alo) @ (Bhi+Blo)^T (fp32 accumulate,
// dropping lo*lo). A:[M,K] bf16 row-major, B:[N,K] bf16 row-major.
// CTA tile 128x128, K-chunk 32, 8 warps (2 x 4), warp tile 64x32.
// SIM: epilogue applies adjacency mask -> sim_masked into C.
// ---------------------------------------------------------------------------
template <bool SIM>
__global__ __launch_bounds__(256, 2)
void hmma_gemm(const __nv_bfloat16* __restrict__ Ahi, const __nv_bfloat16* __restrict__ Alo,
               const __nv_bfloat16* __restrict__ Bhi, const __nv_bfloat16* __restrict__ Blo,
               float* __restrict__ C, int K, int Cld,
               const int* __restrict__ adj)
{
    extern __shared__ char smem[];
    const uint32_t base = smem_u32(smem);

    const int tid  = threadIdx.x;
    const int lane = tid & 31;
    const int wid  = tid >> 5;
    const int warp_m = wid & 1;        // 0..1  -> 64-row slab
    const int warp_n = wid >> 1;       // 0..3  -> 32-col slab
    const int rowBase = blockIdx.y * 128;
    const int colBase = blockIdx.x * 128;

    const __nv_bfloat16* srcs[4] = { Ahi, Alo, Bhi, Blo };
    const int rb[4] = { rowBase, rowBase, colBase, colBase };

    float acc[4][4][4];
#pragma unroll
    for (int mi = 0; mi < 4; mi++)
#pragma unroll
        for (int ni = 0; ni < 4; ni++)
#pragma unroll
            for (int r = 0; r < 4; r++) acc[mi][ni][r] = 0.f;

    const int NC = K >> 5;

    // chunk prefetch: 4 tiles x 128 rows x 64B = 2048 x 16B; 8 per thread
    auto prefetch = [&](int c, int buf) {
#pragma unroll
        for (int it = 0; it < 8; it++) {
            const int t   = it >> 1;                    // compile-time tile id
            const int rem = ((it & 1) << 8) + tid;      // 0..511
            const int row = rem >> 2;
            const int u   = rem & 3;
            const __nv_bfloat16* sp =
                srcs[t] + (size_t)(rb[t] + row) * K + ((size_t)c << 5) + u * 8;
            uint32_t dst = base + (uint32_t)(buf * 4 + t) * 8192u + swz_off(row, u);
            cpasync16(dst, sp);
        }
        cp_commit();
    };

    prefetch(0, 0);

    for (int c = 0; c < NC; c++) {
        const int buf = c & 1;
        if (c + 1 < NC) {
            prefetch(c + 1, buf ^ 1);
            asm volatile("cp.async.wait_group 1;" ::: "memory");
        } else {
            asm volatile("cp.async.wait_group 0;" ::: "memory");
        }
        __syncthreads();

        const uint32_t tAhi = base + (uint32_t)(buf * 4 + 0) * 8192u;
        const uint32_t tAlo = base + (uint32_t)(buf * 4 + 1) * 8192u;
        const uint32_t tBhi = base + (uint32_t)(buf * 4 + 2) * 8192u;
        const uint32_t tBlo = base + (uint32_t)(buf * 4 + 3) * 8192u;

#pragma unroll
        for (int ks = 0; ks < 2; ks++) {
            const int lrow = lane & 15;
            const int lu   = ks * 2 + (lane >> 4);

            uint32_t ah[4][4], bh[4][2], bl[4][2];
#pragma unroll
            for (int mi = 0; mi < 4; mi++)
                ldsm4(ah[mi], tAhi + swz_off(warp_m * 64 + mi * 16 + lrow, lu));
#pragma unroll
            for (int g = 0; g < 2; g++) {
                uint32_t r[4];
                ldsm4(r, tBhi + swz_off(warp_n * 32 + g * 16 + lrow, lu));
                bh[g * 2 + 0][0] = r[0]; bh[g * 2 + 1][0] = r[1];
                bh[g * 2 + 0][1] = r[2]; bh[g * 2 + 1][1] = r[3];
                ldsm4(r, tBlo + swz_off(warp_n * 32 + g * 16 + lrow, lu));
                bl[g * 2 + 0][0] = r[0]; bl[g * 2 + 1][0] = r[1];
                bl[g * 2 + 0][1] = r[2]; bl[g * 2 + 1][1] = r[3];
            }
            // hi*hi and hi*lo
#pragma unroll
            for (int mi = 0; mi < 4; mi++)
#pragma unroll
                for (int ni = 0; ni < 4; ni++) {
                    mma16816(acc[mi][ni], ah[mi], bh[ni]);
                    mma16816(acc[mi][ni], ah[mi], bl[ni]);
                }
            // lo*hi
            uint32_t al[4][4];
#pragma unroll
            for (int mi = 0; mi < 4; mi++)
                ldsm4(al[mi], tAlo + swz_off(warp_m * 64 + mi * 16 + lrow, lu));
#pragma unroll
            for (int mi = 0; mi < 4; mi++)
#pragma unroll
                for (int ni = 0; ni < 4; ni++)
                    mma16816(acc[mi][ni], al[mi], bh[ni]);
        }
        __syncthreads();
    }

    // ---------------- epilogue -------------------------------------------
    const int quad = lane >> 2;
    const int qt   = lane & 3;
    const float NEG_INF = __int_as_float(0xff800000);
#pragma unroll
    for (int mi = 0; mi < 4; mi++) {
#pragma unroll
        for (int ni = 0; ni < 4; ni++) {
            const int r0 = rowBase + warp_m * 64 + mi * 16 + quad;
            const int r1 = r0 + 8;
            const int cc = colBase + warp_n * 32 + ni * 8 + qt * 2;
            const float* a4 = acc[mi][ni];
            if (SIM) {
                int2 m0 = *reinterpret_cast<const int2*>(adj + (size_t)r0 * NN + cc);
                int2 m1 = *reinterpret_cast<const int2*>(adj + (size_t)r1 * NN + cc);
                float2 v0, v1;
                v0.x = (m0.x > 0 || r0 == cc)     ? a4[0] : NEG_INF;
                v0.y = (m0.y > 0 || r0 == cc + 1) ? a4[1] : NEG_INF;
                v1.x = (m1.x > 0 || r1 == cc)     ? a4[2] : NEG_INF;
                v1.y = (m1.y > 0 || r1 == cc + 1) ? a4[3] : NEG_INF;
                *reinterpret_cast<float2*>(C + (size_t)r0 * Cld + cc) = v0;
                *reinterpret_cast<float2*>(C + (size_t)r1 * Cld + cc) = v1;
            } else {
                *reinterpret_cast<float2*>(C + (size_t)r0 * Cld + cc) =
                    make_float2(a4[0], a4[1]);
                *reinterpret_cast<float2*>(C + (size_t)r1 * Cld + cc) =
                    make_float2(a4[2], a4[3]);
            }
        }
    }
}

// ---------------------------------------------------------------------------
// fp32 GEMM (NT) for Wh = h @ W^T.
// ---------------------------------------------------------------------------
__global__ __launch_bounds__(256, 2)
void gemm_wh(const float* __restrict__ A, const float* __restrict__ B,
             float* __restrict__ C)
{
    const int Ncols = DD, K = DD;
    __shared__ float As[16][128];
    __shared__ float Bs[16][128];
    const int tid = threadIdx.x;
    const int tx = tid & 15, ty = tid >> 4;
    const int rowBase = blockIdx.y * 128, colBase = blockIdx.x * 128;

    float acc[8][8];
#pragma unroll
    for (int i = 0; i < 8; i++)
#pragma unroll
        for (int j = 0; j < 8; j++) acc[i][j] = 0.f;

    for (int k0 = 0; k0 < K; k0 += 16) {
#pragma unroll
        for (int l = 0; l < 2; l++) {
            int idx = tid + l * 256;
            int r = idx >> 2, c4 = (idx & 3) << 2;
            float4 va = *reinterpret_cast<const float4*>(A + (size_t)(rowBase + r) * K + k0 + c4);
            As[c4 + 0][r] = va.x; As[c4 + 1][r] = va.y; As[c4 + 2][r] = va.z; As[c4 + 3][r] = va.w;
            float4 vb = *reinterpret_cast<const float4*>(B + (size_t)(colBase + r) * K + k0 + c4);
            Bs[c4 + 0][r] = vb.x; Bs[c4 + 1][r] = vb.y; Bs[c4 + 2][r] = vb.z; Bs[c4 + 3][r] = vb.w;
        }
        __syncthreads();
#pragma unroll
        for (int k = 0; k < 16; k++) {
            float a[8], b[8];
#pragma unroll
            for (int i = 0; i < 8; i++) a[i] = As[k][ty * 8 + i];
#pragma unroll
            for (int j = 0; j < 8; j++) b[j] = Bs[k][tx * 8 + j];
#pragma unroll
            for (int i = 0; i < 8; i++)
#pragma unroll
                for (int j = 0; j < 8; j++) acc[i][j] = fmaf(a[i], b[j], acc[i][j]);
        }
        __syncthreads();
    }
#pragma unroll
    for (int i = 0; i < 8; i++) {
        int row = rowBase + ty * 8 + i;
#pragma unroll
        for (int j = 0; j < 8; j += 4) {
            int col = colBase + tx * 8 + j;
            float4 v = make_float4(acc[i][j], acc[i][j+1], acc[i][j+2], acc[i][j+3]);
            *reinterpret_cast<float4*>(C + (size_t)row * Ncols + col) = v;
        }
    }
}

// ---------------------------------------------------------------------------
// prep: per-row normalize Wh, emit bf16 hi/lo splits. One warp per row.
// ---------------------------------------------------------------------------
__global__ void prep_norm_split(const float* __restrict__ Wh,
                                __nv_bfloat16* __restrict__ hi,
                                __nv_bfloat16* __restrict__ lo)
{
    int row  = blockIdx.x * 8 + (threadIdx.x >> 5);
    int lane = threadIdx.x & 31;
    const float4* r4 = reinterpret_cast<const float4*>(Wh + (size_t)row * DD);

    float4 v[4];
    float ss = 0.f;
#pragma unroll
    for (int i = 0; i < 4; i++) {
        v[i] = r4[lane + i * 32];
        ss = fmaf(v[i].x, v[i].x, ss); ss = fmaf(v[i].y, v[i].y, ss);
        ss = fmaf(v[i].z, v[i].z, ss); ss = fmaf(v[i].w, v[i].w, ss);
    }
#pragma unroll
    for (int off = 16; off > 0; off >>= 1) ss += __shfl_xor_sync(0xffffffffu, ss, off);
    float s = rsqrtf(ss + EPSF);

    __nv_bfloat16* ph = hi + (size_t)row * DD;
    __nv_bfloat16* pl = lo + (size_t)row * DD;
#pragma unroll
    for (int i = 0; i < 4; i++) {
        int col = (lane + i * 32) * 4;
        float x[4] = { v[i].x * s, v[i].y * s, v[i].z * s, v[i].w * s };
#pragma unroll
        for (int j = 0; j < 2; j++) {
            __nv_bfloat16 h0 = __float2bfloat16(x[2*j]);
            __nv_bfloat16 h1 = __float2bfloat16(x[2*j+1]);
            __nv_bfloat16 l0 = __float2bfloat16(x[2*j]   - __bfloat162float(h0));
            __nv_bfloat16 l1 = __float2bfloat16(x[2*j+1] - __bfloat162float(h1));
            *reinterpret_cast<__nv_bfloat162*>(ph + col + 2*j) = __nv_bfloat162(h0, h1);
            *reinterpret_cast<__nv_bfloat162*>(pl + col + 2*j) = __nv_bfloat162(l0, l1);
        }
    }
}

// ---------------------------------------------------------------------------
// tsplit: Bt[d][n] = split(Wh[n][d]) — tiled transpose + bf16 split.
// ---------------------------------------------------------------------------
__global__ void tsplit(const float* __restrict__ Wh,
                       __nv_bfloat16* __restrict__ th,
                       __nv_bfloat16* __restrict__ tl)
{
    __shared__ float t[32][33];
    int bx = blockIdx.x, by = blockIdx.y;
    int tx = threadIdx.x, ty = threadIdx.y;
#pragma unroll
    for (int i = 0; i < 32; i += 8)
        t[ty + i][tx] = Wh[(size_t)(by * 32 + ty + i) * DD + bx * 32 + tx];
    __syncthreads();
#pragma unroll
    for (int i = 0; i < 32; i += 8) {
        float x = t[tx][ty + i];
        __nv_bfloat16 h = __float2bfloat16(x);
        __nv_bfloat16 l = __float2bfloat16(x - __bfloat162float(h));
        size_t o = (size_t)(bx * 32 + ty + i) * NN + by * 32 + tx;
        th[o] = h; tl[o] = l;
    }
}

// ---------------------------------------------------------------------------
// Row softmax over S -> alpha bf16 hi/lo splits.
// ---------------------------------------------------------------------------
__global__ void row_softmax2(const float* __restrict__ S,
                             __nv_bfloat16* __restrict__ ah,
                             __nv_bfloat16* __restrict__ al)
{
    __shared__ float2 red[256];
    const size_t row = blockIdx.x;
    const float* x = S + row * (size_t)NN;
    const int tid = threadIdx.x;

    float m = -1e30f, s = 0.f;
    for (int c = tid; c < NN; c += 256) {
        float v = x[c];
        if (v > m) { s = s * __expf(m - v) + 1.f; m = v; }
        else       { s += __expf(v - m); }
    }
    red[tid] = make_float2(m, s);
    __syncthreads();
    for (int st = 128; st > 0; st >>= 1) {
        if (tid < st) {
            float2 a = red[tid], b = red[tid + st];
            float mm = fmaxf(a.x, b.x);
            red[tid] = make_float2(mm, a.y * __expf(a.x - mm) + b.y * __expf(b.x - mm));
        }
        __syncthreads();
    }
    const float M   = red[0].x;
    const float inv = 1.0f / red[0].y;

    __nv_bfloat16* ph = ah + row * (size_t)NN;
    __nv_bfloat16* pl = al + row * (size_t)NN;
    for (int c = tid * 2; c < NN; c += 512) {
        float2 v = *reinterpret_cast<const float2*>(x + c);
        float e0 = __expf(v.x - M) * inv;
        float e1 = __expf(v.y - M) * inv;
        __nv_bfloat16 h0 = __float2bfloat16(e0), h1 = __float2bfloat16(e1);
        __nv_bfloat16 l0 = __float2bfloat16(e0 - __bfloat162float(h0));
        __nv_bfloat16 l1 = __float2bfloat16(e1 - __bfloat162float(h1));
        *reinterpret_cast<__nv_bfloat162*>(ph + c) = __nv_bfloat162(h0, h1);
        *reinterpret_cast<__nv_bfloat162*>(pl + c) = __nv_bfloat162(l0, l1);
    }
}

// ---------------------------------------------------------------------------
extern "C" void kernel_launch(void* const* d_in, const int* in_sizes, int n_in,
                              void* d_out, int out_size)
{
    const float* h   = (const float*)d_in[0];   // [8192, 512]
    const int*   adj = (const int*)d_in[1];     // [8192, 8192]
    const float* W   = (const float*)d_in[2];   // [512, 512]
    float* out = (float*)d_out;                 // [8192, 512]

    void* p;
    cudaGetSymbolAddress(&p, g_Wh);    float* Wh = (float*)p;
    cudaGetSymbolAddress(&p, g_S);     float* S  = (float*)p;
    cudaGetSymbolAddress(&p, g_An_hi); __nv_bfloat16* Anh = (__nv_bfloat16*)p;
    cudaGetSymbolAddress(&p, g_An_lo); __nv_bfloat16* Anl = (__nv_bfloat16*)p;
    cudaGetSymbolAddress(&p, g_Bt_hi); __nv_bfloat16* Bth = (__nv_bfloat16*)p;
    cudaGetSymbolAddress(&p, g_Bt_lo); __nv_bfloat16* Btl = (__nv_bfloat16*)p;
    cudaGetSymbolAddress(&p, g_a_hi);  __nv_bfloat16* alh = (__nv_bfloat16*)p;
    cudaGetSymbolAddress(&p, g_a_lo);  __nv_bfloat16* all_ = (__nv_bfloat16*)p;

    const int SMEM = 65536;   // 2 buffers x 4 tiles x 8KB
    cudaFuncSetAttribute((const void*)hmma_gemm<true>,
                         cudaFuncAttributeMaxDynamicSharedMemorySize, SMEM);
    cudaFuncSetAttribute((const void*)hmma_gemm<false>,
                         cudaFuncAttributeMaxDynamicSharedMemorySize, SMEM);

    // 1) Wh = h @ W^T (fp32)
    gemm_wh<<<dim3(DD / 128, NN / 128), 256>>>(h, W, Wh);
    // 2) normalized bf16 splits of Wh rows
    prep_norm_split<<<NN / 8, 256>>>(Wh, Anh, Anl);
    // 3) Wh^T bf16 splits (B operand of final GEMM)
    tsplit<<<dim3(DD / 32, NN / 32), dim3(32, 8)>>>(Wh, Bth, Btl);
    // 4) S = masked cosine sim (HMMA split-bf16), tiles 128x128
    hmma_gemm<true><<<dim3(NN / 128, NN / 128), 256, SMEM>>>(
        Anh, Anl, Anh, Anl, S, DD, NN, adj);
    // 5) softmax -> alpha bf16 splits
    row_softmax2<<<NN, 256>>>(S, alh, all_);
    // 6) out = alpha @ Wh (HMMA split-bf16), K = 8192
    hmma_gemm<false><<<dim3(DD / 128, NN / 128), 256, SMEM>>>(
        alh, all_, Bth, Btl, out, NN, DD, nullptr);
}

// round 7
// speedup vs baseline: 3.2352x; 1.2808x over previous
#include <cuda_runtime.h>
#include <cuda_bf16.h>
#include <math.h>
#include <stdint.h>

#define NN 8192
#define DD 512
#define EPSF 1e-8f

// ---------------- scratch (__device__ globals; no allocation) ----------------
__device__ float g_Wh[(size_t)NN * DD];                 // 16.8 MB
__device__ float g_S [(size_t)NN * NN];                 // 268 MB
__device__ __nv_bfloat16 g_An_hi[(size_t)NN * DD];      // normalized Wh (bf16)
__device__ __nv_bfloat16 g_Bt_hi[(size_t)DD * NN];      // Wh^T splits
__device__ __nv_bfloat16 g_Bt_lo[(size_t)DD * NN];
__device__ __nv_bfloat16 g_a_hi [(size_t)NN * NN];      // alpha splits
__device__ __nv_bfloat16 g_a_lo [(size_t)NN * NN];

// ---------------- PTX helpers (baseline PTX, sm_80+) ------------------------
__device__ __forceinline__ uint32_t smem_u32(const void* p) {
    uint32_t a;
    asm("{ .reg .u64 t; cvta.to.shared.u64 t, %1; cvt.u32.u64 %0, t; }"
        : "=r"(a) : "l"(p));
    return a;
}
__device__ __forceinline__ void cpasync16(uint32_t dst, const void* src) {
    asm volatile("cp.async.cg.shared.global [%0], [%1], 16;"
                 :: "r"(dst), "l"(src) : "memory");
}
__device__ __forceinline__ void cp_commit() {
    asm volatile("cp.async.commit_group;" ::: "memory");
}
__device__ __forceinline__ void ldsm4(uint32_t* r, uint32_t addr) {
    asm volatile("ldmatrix.sync.aligned.m8n8.x4.shared.b16 {%0,%1,%2,%3}, [%4];"
                 : "=r"(r[0]), "=r"(r[1]), "=r"(r[2]), "=r"(r[3]) : "r"(addr));
}
__device__ __forceinline__ void mma16816(float* d, const uint32_t* a, const uint32_t* b) {
    asm volatile(
        "mma.sync.aligned.m16n8k16.row.col.f32.bf16.bf16.f32 "
        "{%0,%1,%2,%3}, {%4,%5,%6,%7}, {%8,%9}, {%0,%1,%2,%3};"
        : "+f"(d[0]), "+f"(d[1]), "+f"(d[2]), "+f"(d[3])
        : "r"(a[0]), "r"(a[1]), "r"(a[2]), "r"(a[3]), "r"(b[0]), "r"(b[1]));
}

// swizzled offset in a [rows x 32 bf16] tile (64B pitch, 16B units)
__device__ __forceinline__ uint32_t swz64(int row, int u) {
    return (uint32_t)(row * 64 + ((u ^ ((row >> 1) & 3)) << 4));
}
// swizzled offset in a [rows x 64 bf16] tile (128B pitch, 16B units)
__device__ __forceinline__ uint32_t swz128(int row, int u) {
    return (uint32_t)(row * 128 + ((u ^ (row & 7)) << 4));
}

// ---------------------------------------------------------------------------
// GEMM1: C = A @ B^T, single bf16 term, fp32 accum. A:[M,K], B:[N,K] bf16.
// CTA 128x128, K-chunk 64, 3-stage cp.async pipeline, 8 warps (warp 64x32).
// SIM epilogue: adjacency mask.
// ---------------------------------------------------------------------------
template <bool SIM>
__global__ __launch_bounds__(256, 2)
void hmma_gemm1(const __nv_bfloat16* __restrict__ A, const __nv_bfloat16* __restrict__ B,
                float* __restrict__ C, int K, int Cld, const int* __restrict__ adj)
{
    extern __shared__ char smem[];
    const uint32_t base = smem_u32(smem);

    const int tid  = threadIdx.x;
    const int lane = tid & 31;
    const int wid  = tid >> 5;
    const int warp_m = wid & 1;
    const int warp_n = wid >> 1;
    const int rowBase = blockIdx.y * 128;
    const int colBase = blockIdx.x * 128;

    float acc[4][4][4];
#pragma unroll
    for (int mi = 0; mi < 4; mi++)
#pragma unroll
        for (int ni = 0; ni < 4; ni++)
#pragma unroll
            for (int r = 0; r < 4; r++) acc[mi][ni][r] = 0.f;

    const int NC = K >> 6;     // 64-wide K chunks

    // stage: A tile 128x64 bf16 (16KB) @ +0, B tile @ +16KB; stage stride 32KB
    auto prefetch = [&](int c, int stage) {
#pragma unroll
        for (int it = 0; it < 8; it++) {
            const int t   = it >> 2;                    // 0=A, 1=B
            const int rem = ((it & 3) << 8) + tid;      // 0..1023
            const int row = rem >> 3;
            const int u   = rem & 7;
            const __nv_bfloat16* sp =
                (t ? B + (size_t)(colBase + row) * K : A + (size_t)(rowBase + row) * K)
                + ((size_t)c << 6) + u * 8;
            uint32_t dst = base + (uint32_t)stage * 32768u + (uint32_t)t * 16384u
                         + swz128(row, u);
            cpasync16(dst, sp);
        }
        cp_commit();
    };

    prefetch(0, 0);
    prefetch(1, 1);

    for (int c = 0; c < NC; c++) {
        if (c + 1 < NC) asm volatile("cp.async.wait_group 1;" ::: "memory");
        else            asm volatile("cp.async.wait_group 0;" ::: "memory");
        __syncthreads();
        if (c + 2 < NC) prefetch(c + 2, (c + 2) % 3);

        const uint32_t sA = base + (uint32_t)(c % 3) * 32768u;
        const uint32_t sB = sA + 16384u;
        const int lrow = lane & 15;
#pragma unroll
        for (int ks = 0; ks < 4; ks++) {
            const int lu = ks * 2 + (lane >> 4);
            uint32_t ah[4][4], b[4][2];
#pragma unroll
            for (int mi = 0; mi < 4; mi++) {
                int r = warp_m * 64 + mi * 16 + lrow;
                ldsm4(ah[mi], sA + swz128(r, lu));
            }
#pragma unroll
            for (int g = 0; g < 2; g++) {
                int r = warp_n * 32 + g * 16 + lrow;
                uint32_t t4[4];
                ldsm4(t4, sB + swz128(r, lu));
                b[g * 2 + 0][0] = t4[0]; b[g * 2 + 1][0] = t4[1];
                b[g * 2 + 0][1] = t4[2]; b[g * 2 + 1][1] = t4[3];
            }
#pragma unroll
            for (int mi = 0; mi < 4; mi++)
#pragma unroll
                for (int ni = 0; ni < 4; ni++)
                    mma16816(acc[mi][ni], ah[mi], b[ni]);
        }
    }

    // epilogue
    const int quad = lane >> 2;
    const int qt   = lane & 3;
    const float NEG_INF = __int_as_float(0xff800000);
#pragma unroll
    for (int mi = 0; mi < 4; mi++) {
#pragma unroll
        for (int ni = 0; ni < 4; ni++) {
            const int r0 = rowBase + warp_m * 64 + mi * 16 + quad;
            const int r1 = r0 + 8;
            const int cc = colBase + warp_n * 32 + ni * 8 + qt * 2;
            const float* a4 = acc[mi][ni];
            if (SIM) {
                int2 m0 = *reinterpret_cast<const int2*>(adj + (size_t)r0 * NN + cc);
                int2 m1 = *reinterpret_cast<const int2*>(adj + (size_t)r1 * NN + cc);
                float2 v0, v1;
                v0.x = (m0.x > 0 || r0 == cc)     ? a4[0] : NEG_INF;
                v0.y = (m0.y > 0 || r0 == cc + 1) ? a4[1] : NEG_INF;
                v1.x = (m1.x > 0 || r1 == cc)     ? a4[2] : NEG_INF;
                v1.y = (m1.y > 0 || r1 == cc + 1) ? a4[3] : NEG_INF;
                *reinterpret_cast<float2*>(C + (size_t)r0 * Cld + cc) = v0;
                *reinterpret_cast<float2*>(C + (size_t)r1 * Cld + cc) = v1;
            } else {
                *reinterpret_cast<float2*>(C + (size_t)r0 * Cld + cc) =
                    make_float2(a4[0], a4[1]);
                *reinterpret_cast<float2*>(C + (size_t)r1 * Cld + cc) =
                    make_float2(a4[2], a4[3]);
            }
        }
    }
}

// ---------------------------------------------------------------------------
// GEMM2: C = (Ahi+Alo) @ (Bhi+Blo)^T, 3-term split bf16, fp32 accum.
// CTA 128x128, K-chunk 32, 3-stage cp.async pipeline.
// ---------------------------------------------------------------------------
__global__ __launch_bounds__(256, 2)
void hmma_gemm3(const __nv_bfloat16* __restrict__ Ahi, const __nv_bfloat16* __restrict__ Alo,
                const __nv_bfloat16* __restrict__ Bhi, const __nv_bfloat16* __restrict__ Blo,
                float* __restrict__ C, int K, int Cld)
{
    extern __shared__ char smem[];
    const uint32_t base = smem_u32(smem);

    const int tid  = threadIdx.x;
    const int lane = tid & 31;
    const int wid  = tid >> 5;
    const int warp_m = wid & 1;
    const int warp_n = wid >> 1;
    const int rowBase = blockIdx.y * 128;
    const int colBase = blockIdx.x * 128;

    const __nv_bfloat16* srcs[4] = { Ahi, Alo, Bhi, Blo };
    const int rb[4] = { rowBase, rowBase, colBase, colBase };

    float acc[4][4][4];
#pragma unroll
    for (int mi = 0; mi < 4; mi++)
#pragma unroll
        for (int ni = 0; ni < 4; ni++)
#pragma unroll
            for (int r = 0; r < 4; r++) acc[mi][ni][r] = 0.f;

    const int NC = K >> 5;     // 32-wide K chunks

    // stage: 4 tiles x 128 rows x 64B = 8KB each; stage stride 32KB
    auto prefetch = [&](int c, int stage) {
#pragma unroll
        for (int it = 0; it < 8; it++) {
            const int t   = it >> 1;
            const int rem = ((it & 1) << 8) + tid;      // 0..511
            const int row = rem >> 2;
            const int u   = rem & 3;
            const __nv_bfloat16* sp =
                srcs[t] + (size_t)(rb[t] + row) * K + ((size_t)c << 5) + u * 8;
            uint32_t dst = base + (uint32_t)stage * 32768u + (uint32_t)t * 8192u
                         + swz64(row, u);
            cpasync16(dst, sp);
        }
        cp_commit();
    };

    prefetch(0, 0);
    prefetch(1, 1);

    for (int c = 0; c < NC; c++) {
        if (c + 1 < NC) asm volatile("cp.async.wait_group 1;" ::: "memory");
        else            asm volatile("cp.async.wait_group 0;" ::: "memory");
        __syncthreads();
        if (c + 2 < NC) prefetch(c + 2, (c + 2) % 3);

        const uint32_t st   = base + (uint32_t)(c % 3) * 32768u;
        const uint32_t tAhi = st;
        const uint32_t tAlo = st + 8192u;
        const uint32_t tBhi = st + 16384u;
        const uint32_t tBlo = st + 24576u;
        const int lrow = lane & 15;

#pragma unroll
        for (int ks = 0; ks < 2; ks++) {
            const int lu = ks * 2 + (lane >> 4);

            uint32_t ah[4][4], bh[4][2], bl[4][2];
#pragma unroll
            for (int mi = 0; mi < 4; mi++)
                ldsm4(ah[mi], tAhi + swz64(warp_m * 64 + mi * 16 + lrow, lu));
#pragma unroll
            for (int g = 0; g < 2; g++) {
                uint32_t r[4];
                ldsm4(r, tBhi + swz64(warp_n * 32 + g * 16 + lrow, lu));
                bh[g * 2 + 0][0] = r[0]; bh[g * 2 + 1][0] = r[1];
                bh[g * 2 + 0][1] = r[2]; bh[g * 2 + 1][1] = r[3];
                ldsm4(r, tBlo + swz64(warp_n * 32 + g * 16 + lrow, lu));
                bl[g * 2 + 0][0] = r[0]; bl[g * 2 + 1][0] = r[1];
                bl[g * 2 + 0][1] = r[2]; bl[g * 2 + 1][1] = r[3];
            }
#pragma unroll
            for (int mi = 0; mi < 4; mi++)
#pragma unroll
                for (int ni = 0; ni < 4; ni++) {
                    mma16816(acc[mi][ni], ah[mi], bh[ni]);
                    mma16816(acc[mi][ni], ah[mi], bl[ni]);
                }
            uint32_t al[4][4];
#pragma unroll
            for (int mi = 0; mi < 4; mi++)
                ldsm4(al[mi], tAlo + swz64(warp_m * 64 + mi * 16 + lrow, lu));
#pragma unroll
            for (int mi = 0; mi < 4; mi++)
#pragma unroll
                for (int ni = 0; ni < 4; ni++)
                    mma16816(acc[mi][ni], al[mi], bh[ni]);
        }
    }

    // epilogue
    const int quad = lane >> 2;
    const int qt   = lane & 3;
#pragma unroll
    for (int mi = 0; mi < 4; mi++) {
#pragma unroll
        for (int ni = 0; ni < 4; ni++) {
            const int r0 = rowBase + warp_m * 64 + mi * 16 + quad;
            const int r1 = r0 + 8;
            const int cc = colBase + warp_n * 32 + ni * 8 + qt * 2;
            const float* a4 = acc[mi][ni];
            *reinterpret_cast<float2*>(C + (size_t)r0 * Cld + cc) =
                make_float2(a4[0], a4[1]);
            *reinterpret_cast<float2*>(C + (size_t)r1 * Cld + cc) =
                make_float2(a4[2], a4[3]);
        }
    }
}

// ---------------------------------------------------------------------------
// fp32 GEMM (NT) for Wh = h @ W^T.
// ---------------------------------------------------------------------------
__global__ __launch_bounds__(256, 2)
void gemm_wh(const float* __restrict__ A, const float* __restrict__ B,
             float* __restrict__ C)
{
    const int Ncols = DD, K = DD;
    __shared__ float As[16][128];
    __shared__ float Bs[16][128];
    const int tid = threadIdx.x;
    const int tx = tid & 15, ty = tid >> 4;
    const int rowBase = blockIdx.y * 128, colBase = blockIdx.x * 128;

    float acc[8][8];
#pragma unroll
    for (int i = 0; i < 8; i++)
#pragma unroll
        for (int j = 0; j < 8; j++) acc[i][j] = 0.f;

    for (int k0 = 0; k0 < K; k0 += 16) {
#pragma unroll
        for (int l = 0; l < 2; l++) {
            int idx = tid + l * 256;
            int r = idx >> 2, c4 = (idx & 3) << 2;
            float4 va = *reinterpret_cast<const float4*>(A + (size_t)(rowBase + r) * K + k0 + c4);
            As[c4 + 0][r] = va.x; As[c4 + 1][r] = va.y; As[c4 + 2][r] = va.z; As[c4 + 3][r] = va.w;
            float4 vb = *reinterpret_cast<const float4*>(B + (size_t)(colBase + r) * K + k0 + c4);
            Bs[c4 + 0][r] = vb.x; Bs[c4 + 1][r] = vb.y; Bs[c4 + 2][r] = vb.z; Bs[c4 + 3][r] = vb.w;
        }
        __syncthreads();
#pragma unroll
        for (int k = 0; k < 16; k++) {
            float a[8], b[8];
#pragma unroll
            for (int i = 0; i < 8; i++) a[i] = As[k][ty * 8 + i];
#pragma unroll
            for (int j = 0; j < 8; j++) b[j] = Bs[k][tx * 8 + j];
#pragma unroll
            for (int i = 0; i < 8; i++)
#pragma unroll
                for (int j = 0; j < 8; j++) acc[i][j] = fmaf(a[i], b[j], acc[i][j]);
        }
        __syncthreads();
    }
#pragma unroll
    for (int i = 0; i < 8; i++) {
        int row = rowBase + ty * 8 + i;
#pragma unroll
        for (int j = 0; j < 8; j += 4) {
            int col = colBase + tx * 8 + j;
            float4 v = make_float4(acc[i][j], acc[i][j+1], acc[i][j+2], acc[i][j+3]);
            *reinterpret_cast<float4*>(C + (size_t)row * Ncols + col) = v;
        }
    }
}

// ---------------------------------------------------------------------------
// prep: per-row normalize Wh, emit bf16 (hi only). One warp per row.
// ---------------------------------------------------------------------------
__global__ void prep_norm_bf16(const float* __restrict__ Wh,
                               __nv_bfloat16* __restrict__ hi)
{
    int row  = blockIdx.x * 8 + (threadIdx.x >> 5);
    int lane = threadIdx.x & 31;
    const float4* r4 = reinterpret_cast<const float4*>(Wh + (size_t)row * DD);

    float4 v[4];
    float ss = 0.f;
#pragma unroll
    for (int i = 0; i < 4; i++) {
        v[i] = r4[lane + i * 32];
        ss = fmaf(v[i].x, v[i].x, ss); ss = fmaf(v[i].y, v[i].y, ss);
        ss = fmaf(v[i].z, v[i].z, ss); ss = fmaf(v[i].w, v[i].w, ss);
    }
#pragma unroll
    for (int off = 16; off > 0; off >>= 1) ss += __shfl_xor_sync(0xffffffffu, ss, off);
    float s = rsqrtf(ss + EPSF);

    __nv_bfloat16* ph = hi + (size_t)row * DD;
#pragma unroll
    for (int i = 0; i < 4; i++) {
        int col = (lane + i * 32) * 4;
        *reinterpret_cast<__nv_bfloat162*>(ph + col) =
            __nv_bfloat162(__float2bfloat16(v[i].x * s), __float2bfloat16(v[i].y * s));
        *reinterpret_cast<__nv_bfloat162*>(ph + col + 2) =
            __nv_bfloat162(__float2bfloat16(v[i].z * s), __float2bfloat16(v[i].w * s));
    }
}

// ---------------------------------------------------------------------------
// tsplit: Bt[d][n] = split(Wh[n][d]) — tiled transpose + bf16 split.
// ---------------------------------------------------------------------------
__global__ void tsplit(const float* __restrict__ Wh,
                       __nv_bfloat16* __restrict__ th,
                       __nv_bfloat16* __restrict__ tl)
{
    __shared__ float t[32][33];
    int bx = blockIdx.x, by = blockIdx.y;
    int tx = threadIdx.x, ty = threadIdx.y;
#pragma unroll
    for (int i = 0; i < 32; i += 8)
        t[ty + i][tx] = Wh[(size_t)(by * 32 + ty + i) * DD + bx * 32 + tx];
    __syncthreads();
#pragma unroll
    for (int i = 0; i < 32; i += 8) {
        float x = t[tx][ty + i];
        __nv_bfloat16 h = __float2bfloat16(x);
        __nv_bfloat16 l = __float2bfloat16(x - __bfloat162float(h));
        size_t o = (size_t)(bx * 32 + ty + i) * NN + by * 32 + tx;
        th[o] = h; tl[o] = l;
    }
}

// ---------------------------------------------------------------------------
// Row softmax over S -> alpha bf16 hi/lo splits.
// ---------------------------------------------------------------------------
__global__ void row_softmax2(const float* __restrict__ S,
                             __nv_bfloat16* __restrict__ ah,
                             __nv_bfloat16* __restrict__ al)
{
    __shared__ float2 red[256];
    const size_t row = blockIdx.x;
    const float* x = S + row * (size_t)NN;
    const int tid = threadIdx.x;

    float m = -1e30f, s = 0.f;
    for (int c = tid; c < NN; c += 256) {
        float v = x[c];
        if (v > m) { s = s * __expf(m - v) + 1.f; m = v; }
        else       { s += __expf(v - m); }
    }
    red[tid] = make_float2(m, s);
    __syncthreads();
    for (int st = 128; st > 0; st >>= 1) {
        if (tid < st) {
            float2 a = red[tid], b = red[tid + st];
            float mm = fmaxf(a.x, b.x);
            red[tid] = make_float2(mm, a.y * __expf(a.x - mm) + b.y * __expf(b.x - mm));
        }
        __syncthreads();
    }
    const float M   = red[0].x;
    const float inv = 1.0f / red[0].y;

    __nv_bfloat16* ph = ah + row * (size_t)NN;
    __nv_bfloat16* pl = al + row * (size_t)NN;
    for (int c = tid * 2; c < NN; c += 512) {
        float2 v = *reinterpret_cast<const float2*>(x + c);
        float e0 = __expf(v.x - M) * inv;
        float e1 = __expf(v.y - M) * inv;
        __nv_bfloat16 h0 = __float2bfloat16(e0), h1 = __float2bfloat16(e1);
        __nv_bfloat16 l0 = __float2bfloat16(e0 - __bfloat162float(h0));
        __nv_bfloat16 l1 = __float2bfloat16(e1 - __bfloat162float(h1));
        *reinterpret_cast<__nv_bfloat162*>(ph + c) = __nv_bfloat162(h0, h1);
        *reinterpret_cast<__nv_bfloat162*>(pl + c) = __nv_bfloat162(l0, l1);
    }
}

// ---------------------------------------------------------------------------
extern "C" void kernel_launch(void* const* d_in, const int* in_sizes, int n_in,
                              void* d_out, int out_size)
{
    const float* h   = (const float*)d_in[0];   // [8192, 512]
    const int*   adj = (const int*)d_in[1];     // [8192, 8192]
    const float* W   = (const float*)d_in[2];   // [512, 512]
    float* out = (float*)d_out;                 // [8192, 512]

    void* p;
    cudaGetSymbolAddress(&p, g_Wh);    float* Wh = (float*)p;
    cudaGetSymbolAddress(&p, g_S);     float* S  = (float*)p;
    cudaGetSymbolAddress(&p, g_An_hi); __nv_bfloat16* Anh = (__nv_bfloat16*)p;
    cudaGetSymbolAddress(&p, g_Bt_hi); __nv_bfloat16* Bth = (__nv_bfloat16*)p;
    cudaGetSymbolAddress(&p, g_Bt_lo); __nv_bfloat16* Btl = (__nv_bfloat16*)p;
    cudaGetSymbolAddress(&p, g_a_hi);  __nv_bfloat16* alh = (__nv_bfloat16*)p;
    cudaGetSymbolAddress(&p, g_a_lo);  __nv_bfloat16* all_ = (__nv_bfloat16*)p;

    const int SMEM = 98304;   // 3 stages x 32KB
    cudaFuncSetAttribute((const void*)hmma_gemm1<true>,
                         cudaFuncAttributeMaxDynamicSharedMemorySize, SMEM);
    cudaFuncSetAttribute((const void*)hmma_gemm3,
                         cudaFuncAttributeMaxDynamicSharedMemorySize, SMEM);

    // 1) Wh = h @ W^T (fp32)
    gemm_wh<<<dim3(DD / 128, NN / 128), 256>>>(h, W, Wh);
    // 2) normalized Wh rows -> bf16
    prep_norm_bf16<<<NN / 8, 256>>>(Wh, Anh);
    // 3) Wh^T bf16 splits (B operand of final GEMM)
    tsplit<<<dim3(DD / 32, NN / 32), dim3(32, 8)>>>(Wh, Bth, Btl);
    // 4) S = masked cosine sim (single-term bf16 HMMA)
    hmma_gemm1<true><<<dim3(NN / 128, NN / 128), 256, SMEM>>>(
        Anh, Anh, S, DD, NN, adj);
    // 5) softmax -> alpha bf16 splits
    row_softmax2<<<NN, 256>>>(S, alh, all_);
    // 6) out = alpha @ Wh (3-term split bf16 HMMA), K = 8192
    hmma_gemm3<<<dim3(DD / 128, NN / 128), 256, SMEM>>>(
        alh, all_, Bth, Btl, out, NN, DD);
}

// round 8
// speedup vs baseline: 4.4292x; 1.3691x over previous
#include <cuda_runtime.h>
#include <cuda_fp16.h>
#include <math.h>
#include <stdint.h>

#define NN 8192
#define DD 512
#define EPSF 1e-8f

// ---------------- scratch (__device__ globals; no allocation) ----------------
__device__ float  g_Wh [(size_t)NN * DD];          // fp32 Wh
__device__ __half g_hh [(size_t)NN * DD];          // h splits
__device__ __half g_hl [(size_t)NN * DD];
__device__ __half g_wsh[(size_t)DD * DD];          // W splits
__device__ __half g_wsl[(size_t)DD * DD];
__device__ __half g_An [(size_t)NN * DD];          // normalized Wh (fp16)
__device__ __half g_Bth[(size_t)DD * NN];          // Wh^T splits (fp16)
__device__ __half g_Btl[(size_t)DD * NN];
__device__ __half g_p  [(size_t)NN * NN];          // p = exp(sim-1) masked (134MB)
__device__ float  g_inv[NN];                       // 1 / row sum

// ---------------- PTX helpers (baseline PTX, sm_80+) ------------------------
__device__ __forceinline__ uint32_t smem_u32(const void* p) {
    uint32_t a;
    asm("{ .reg .u64 t; cvta.to.shared.u64 t, %1; cvt.u32.u64 %0, t; }"
        : "=r"(a) : "l"(p));
    return a;
}
__device__ __forceinline__ void cpasync16(uint32_t dst, const void* src) {
    asm volatile("cp.async.cg.shared.global [%0], [%1], 16;"
                 :: "r"(dst), "l"(src) : "memory");
}
__device__ __forceinline__ void cp_commit() {
    asm volatile("cp.async.commit_group;" ::: "memory");
}
__device__ __forceinline__ void ldsm4(uint32_t* r, uint32_t addr) {
    asm volatile("ldmatrix.sync.aligned.m8n8.x4.shared.b16 {%0,%1,%2,%3}, [%4];"
                 : "=r"(r[0]), "=r"(r[1]), "=r"(r[2]), "=r"(r[3]) : "r"(addr));
}
__device__ __forceinline__ void mma16816h(float* d, const uint32_t* a, const uint32_t* b) {
    asm volatile(
        "mma.sync.aligned.m16n8k16.row.col.f32.f16.f16.f32 "
        "{%0,%1,%2,%3}, {%4,%5,%6,%7}, {%8,%9}, {%0,%1,%2,%3};"
        : "+f"(d[0]), "+f"(d[1]), "+f"(d[2]), "+f"(d[3])
        : "r"(a[0]), "r"(a[1]), "r"(a[2]), "r"(a[3]), "r"(b[0]), "r"(b[1]));
}

// swizzled offset in a [rows x 32 f16] tile (64B pitch, 16B units)
__device__ __forceinline__ uint32_t swz64(int row, int u) {
    return (uint32_t)(row * 64 + ((u ^ ((row >> 1) & 3)) << 4));
}
// swizzled offset in a [rows x 64 f16] tile (128B pitch, 16B units)
__device__ __forceinline__ uint32_t swz128(int row, int u) {
    return (uint32_t)(row * 128 + ((u ^ (row & 7)) << 4));
}

// ---------------------------------------------------------------------------
// split: x -> fp16 hi + fp16 lo
// ---------------------------------------------------------------------------
__global__ void split_hl(const float* __restrict__ x, __half* __restrict__ hi,
                         __half* __restrict__ lo, int n)
{
    int i = blockIdx.x * blockDim.x + threadIdx.x;
    if (i < n) {
        float v = x[i];
        __half h = __float2half_rn(v);
        hi[i] = h;
        lo[i] = __float2half_rn(v - __half2float(h));
    }
}

// ---------------------------------------------------------------------------
// 3-term fp16-split GEMM (NT): C = (Ahi+Alo)@(Bhi+Blo)^T  -> fp32 C.
// CTA 128x128, K-chunk 32, 3-stage pipeline. (used for Wh = h @ W^T)
// ---------------------------------------------------------------------------
__global__ __launch_bounds__(256, 2)
void hmma3h(const __half* __restrict__ Ahi, const __half* __restrict__ Alo,
            const __half* __restrict__ Bhi, const __half* __restrict__ Blo,
            float* __restrict__ C, int K, int Cld)
{
    extern __shared__ char smem[];
    const uint32_t base = smem_u32(smem);

    const int tid  = threadIdx.x;
    const int lane = tid & 31;
    const int wid  = tid >> 5;
    const int warp_m = wid & 1;
    const int warp_n = wid >> 1;
    const int rowBase = blockIdx.y * 128;
    const int colBase = blockIdx.x * 128;

    const __half* srcs[4] = { Ahi, Alo, Bhi, Blo };
    const int rb[4] = { rowBase, rowBase, colBase, colBase };

    float acc[4][4][4];
#pragma unroll
    for (int mi = 0; mi < 4; mi++)
#pragma unroll
        for (int ni = 0; ni < 4; ni++)
#pragma unroll
            for (int r = 0; r < 4; r++) acc[mi][ni][r] = 0.f;

    const int NC = K >> 5;

    auto prefetch = [&](int c, int stage) {
#pragma unroll
        for (int it = 0; it < 8; it++) {
            const int t   = it >> 1;
            const int rem = ((it & 1) << 8) + tid;
            const int row = rem >> 2;
            const int u   = rem & 3;
            const __half* sp =
                srcs[t] + (size_t)(rb[t] + row) * K + ((size_t)c << 5) + u * 8;
            uint32_t dst = base + (uint32_t)stage * 32768u + (uint32_t)t * 8192u
                         + swz64(row, u);
            cpasync16(dst, sp);
        }
        cp_commit();
    };

    prefetch(0, 0);
    prefetch(1, 1);

    for (int c = 0; c < NC; c++) {
        if (c + 1 < NC) asm volatile("cp.async.wait_group 1;" ::: "memory");
        else            asm volatile("cp.async.wait_group 0;" ::: "memory");
        __syncthreads();
        if (c + 2 < NC) prefetch(c + 2, (c + 2) % 3);

        const uint32_t st   = base + (uint32_t)(c % 3) * 32768u;
        const uint32_t tAhi = st;
        const uint32_t tAlo = st + 8192u;
        const uint32_t tBhi = st + 16384u;
        const uint32_t tBlo = st + 24576u;
        const int lrow = lane & 15;

#pragma unroll
        for (int ks = 0; ks < 2; ks++) {
            const int lu = ks * 2 + (lane >> 4);
            uint32_t ah[4][4], bh[4][2], bl[4][2];
#pragma unroll
            for (int mi = 0; mi < 4; mi++)
                ldsm4(ah[mi], tAhi + swz64(warp_m * 64 + mi * 16 + lrow, lu));
#pragma unroll
            for (int g = 0; g < 2; g++) {
                uint32_t r[4];
                ldsm4(r, tBhi + swz64(warp_n * 32 + g * 16 + lrow, lu));
                bh[g * 2 + 0][0] = r[0]; bh[g * 2 + 1][0] = r[1];
                bh[g * 2 + 0][1] = r[2]; bh[g * 2 + 1][1] = r[3];
                ldsm4(r, tBlo + swz64(warp_n * 32 + g * 16 + lrow, lu));
                bl[g * 2 + 0][0] = r[0]; bl[g * 2 + 1][0] = r[1];
                bl[g * 2 + 0][1] = r[2]; bl[g * 2 + 1][1] = r[3];
            }
#pragma unroll
            for (int mi = 0; mi < 4; mi++)
#pragma unroll
                for (int ni = 0; ni < 4; ni++) {
                    mma16816h(acc[mi][ni], ah[mi], bh[ni]);
                    mma16816h(acc[mi][ni], ah[mi], bl[ni]);
                }
            uint32_t al[4][4];
#pragma unroll
            for (int mi = 0; mi < 4; mi++)
                ldsm4(al[mi], tAlo + swz64(warp_m * 64 + mi * 16 + lrow, lu));
#pragma unroll
            for (int mi = 0; mi < 4; mi++)
#pragma unroll
                for (int ni = 0; ni < 4; ni++)
                    mma16816h(acc[mi][ni], al[mi], bh[ni]);
        }
    }

    const int quad = lane >> 2;
    const int qt   = lane & 3;
#pragma unroll
    for (int mi = 0; mi < 4; mi++) {
#pragma unroll
        for (int ni = 0; ni < 4; ni++) {
            const int r0 = rowBase + warp_m * 64 + mi * 16 + quad;
            const int r1 = r0 + 8;
            const int cc = colBase + warp_n * 32 + ni * 8 + qt * 2;
            const float* a4 = acc[mi][ni];
            *reinterpret_cast<float2*>(C + (size_t)r0 * Cld + cc) =
                make_float2(a4[0], a4[1]);
            *reinterpret_cast<float2*>(C + (size_t)r1 * Cld + cc) =
                make_float2(a4[2], a4[3]);
        }
    }
}

// ---------------------------------------------------------------------------
// SIM GEMM: sim = An @ An^T (single fp16 term), epilogue:
//   p = (adj>0 || diag) ? exp(sim - 1) : 0   -> fp16 P.
// CTA 128x128, K-chunk 64, 3-stage pipeline.
// ---------------------------------------------------------------------------
__global__ __launch_bounds__(256, 2)
void hmma_sim(const __half* __restrict__ A, __half* __restrict__ P,
              int K, const int* __restrict__ adj)
{
    extern __shared__ char smem[];
    const uint32_t base = smem_u32(smem);

    const int tid  = threadIdx.x;
    const int lane = tid & 31;
    const int wid  = tid >> 5;
    const int warp_m = wid & 1;
    const int warp_n = wid >> 1;
    const int rowBase = blockIdx.y * 128;
    const int colBase = blockIdx.x * 128;

    float acc[4][4][4];
#pragma unroll
    for (int mi = 0; mi < 4; mi++)
#pragma unroll
        for (int ni = 0; ni < 4; ni++)
#pragma unroll
            for (int r = 0; r < 4; r++) acc[mi][ni][r] = 0.f;

    const int NC = K >> 6;

    auto prefetch = [&](int c, int stage) {
#pragma unroll
        for (int it = 0; it < 8; it++) {
            const int t   = it >> 2;                    // 0=A rows, 1=B rows
            const int rem = ((it & 3) << 8) + tid;      // 0..1023
            const int row = rem >> 3;
            const int u   = rem & 7;
            const __half* sp = A + (size_t)((t ? colBase : rowBase) + row) * K
                             + ((size_t)c << 6) + u * 8;
            uint32_t dst = base + (uint32_t)stage * 32768u + (uint32_t)t * 16384u
                         + swz128(row, u);
            cpasync16(dst, sp);
        }
        cp_commit();
    };

    prefetch(0, 0);
    prefetch(1, 1);

    for (int c = 0; c < NC; c++) {
        if (c + 1 < NC) asm volatile("cp.async.wait_group 1;" ::: "memory");
        else            asm volatile("cp.async.wait_group 0;" ::: "memory");
        __syncthreads();
        if (c + 2 < NC) prefetch(c + 2, (c + 2) % 3);

        const uint32_t sA = base + (uint32_t)(c % 3) * 32768u;
        const uint32_t sB = sA + 16384u;
        const int lrow = lane & 15;
#pragma unroll
        for (int ks = 0; ks < 4; ks++) {
            const int lu = ks * 2 + (lane >> 4);
            uint32_t ah[4][4], b[4][2];
#pragma unroll
            for (int mi = 0; mi < 4; mi++)
                ldsm4(ah[mi], sA + swz128(warp_m * 64 + mi * 16 + lrow, lu));
#pragma unroll
            for (int g = 0; g < 2; g++) {
                uint32_t t4[4];
                ldsm4(t4, sB + swz128(warp_n * 32 + g * 16 + lrow, lu));
                b[g * 2 + 0][0] = t4[0]; b[g * 2 + 1][0] = t4[1];
                b[g * 2 + 0][1] = t4[2]; b[g * 2 + 1][1] = t4[3];
            }
#pragma unroll
            for (int mi = 0; mi < 4; mi++)
#pragma unroll
                for (int ni = 0; ni < 4; ni++)
                    mma16816h(acc[mi][ni], ah[mi], b[ni]);
        }
    }

    // epilogue: mask + exp(sim - 1) -> fp16
    const int quad = lane >> 2;
    const int qt   = lane & 3;
#pragma unroll
    for (int mi = 0; mi < 4; mi++) {
#pragma unroll
        for (int ni = 0; ni < 4; ni++) {
            const int r0 = rowBase + warp_m * 64 + mi * 16 + quad;
            const int r1 = r0 + 8;
            const int cc = colBase + warp_n * 32 + ni * 8 + qt * 2;
            const float* a4 = acc[mi][ni];
            int2 m0 = *reinterpret_cast<const int2*>(adj + (size_t)r0 * NN + cc);
            int2 m1 = *reinterpret_cast<const int2*>(adj + (size_t)r1 * NN + cc);
            float p00 = (m0.x > 0 || r0 == cc)     ? __expf(a4[0] - 1.f) : 0.f;
            float p01 = (m0.y > 0 || r0 == cc + 1) ? __expf(a4[1] - 1.f) : 0.f;
            float p10 = (m1.x > 0 || r1 == cc)     ? __expf(a4[2] - 1.f) : 0.f;
            float p11 = (m1.y > 0 || r1 == cc + 1) ? __expf(a4[3] - 1.f) : 0.f;
            *reinterpret_cast<__half2*>(P + (size_t)r0 * NN + cc) =
                __floats2half2_rn(p00, p01);
            *reinterpret_cast<__half2*>(P + (size_t)r1 * NN + cc) =
                __floats2half2_rn(p10, p11);
        }
    }
}

// ---------------------------------------------------------------------------
// AV GEMM: out = (P @ (Bhi+Blo)^T) * inv[row]. 2-term fp16, fp32 accum.
// CTA 128x128, K-chunk 64, 2-stage pipeline (48KB/stage).
// ---------------------------------------------------------------------------
__global__ __launch_bounds__(256, 2)
void hmma_av(const __half* __restrict__ P,
             const __half* __restrict__ Bhi, const __half* __restrict__ Blo,
             float* __restrict__ C, int K, int Cld, const float* __restrict__ inv)
{
    extern __shared__ char smem[];
    const uint32_t base = smem_u32(smem);

    const int tid  = threadIdx.x;
    const int lane = tid & 31;
    const int wid  = tid >> 5;
    const int warp_m = wid & 1;
    const int warp_n = wid >> 1;
    const int rowBase = blockIdx.y * 128;
    const int colBase = blockIdx.x * 128;

    const __half* srcs[3] = { P, Bhi, Blo };
    const int rb[3] = { rowBase, colBase, colBase };

    float acc[4][4][4];
#pragma unroll
    for (int mi = 0; mi < 4; mi++)
#pragma unroll
        for (int ni = 0; ni < 4; ni++)
#pragma unroll
            for (int r = 0; r < 4; r++) acc[mi][ni][r] = 0.f;

    const int NC = K >> 6;

    // stage: P 16KB @ +0, Bhi 16KB @ +16K, Blo 16KB @ +32K; stride 48KB
    auto prefetch = [&](int c, int stage) {
#pragma unroll
        for (int it = 0; it < 12; it++) {
            const int t   = it >> 2;                    // tile 0..2
            const int rem = ((it & 3) << 8) + tid;      // 0..1023
            const int row = rem >> 3;
            const int u   = rem & 7;
            const __half* sp =
                srcs[t] + (size_t)(rb[t] + row) * K + ((size_t)c << 6) + u * 8;
            uint32_t dst = base + (uint32_t)stage * 49152u + (uint32_t)t * 16384u
                         + swz128(row, u);
            cpasync16(dst, sp);
        }
        cp_commit();
    };

    prefetch(0, 0);

    for (int c = 0; c < NC; c++) {
        asm volatile("cp.async.wait_group 0;" ::: "memory");
        __syncthreads();
        if (c + 1 < NC) prefetch(c + 1, (c + 1) & 1);

        const uint32_t st  = base + (uint32_t)(c & 1) * 49152u;
        const uint32_t sP  = st;
        const uint32_t sBh = st + 16384u;
        const uint32_t sBl = st + 32768u;
        const int lrow = lane & 15;

#pragma unroll
        for (int ks = 0; ks < 4; ks++) {
            const int lu = ks * 2 + (lane >> 4);
            uint32_t ap[4][4], bh[4][2], bl[4][2];
#pragma unroll
            for (int mi = 0; mi < 4; mi++)
                ldsm4(ap[mi], sP + swz128(warp_m * 64 + mi * 16 + lrow, lu));
#pragma unroll
            for (int g = 0; g < 2; g++) {
                uint32_t r[4];
                ldsm4(r, sBh + swz128(warp_n * 32 + g * 16 + lrow, lu));
                bh[g * 2 + 0][0] = r[0]; bh[g * 2 + 1][0] = r[1];
                bh[g * 2 + 0][1] = r[2]; bh[g * 2 + 1][1] = r[3];
                ldsm4(r, sBl + swz128(warp_n * 32 + g * 16 + lrow, lu));
                bl[g * 2 + 0][0] = r[0]; bl[g * 2 + 1][0] = r[1];
                bl[g * 2 + 0][1] = r[2]; bl[g * 2 + 1][1] = r[3];
            }
#pragma unroll
            for (int mi = 0; mi < 4; mi++)
#pragma unroll
                for (int ni = 0; ni < 4; ni++) {
                    mma16816h(acc[mi][ni], ap[mi], bh[ni]);
                    mma16816h(acc[mi][ni], ap[mi], bl[ni]);
                }
        }
    }

    const int quad = lane >> 2;
    const int qt   = lane & 3;
#pragma unroll
    for (int mi = 0; mi < 4; mi++) {
        const int r0 = rowBase + warp_m * 64 + mi * 16 + quad;
        const int r1 = r0 + 8;
        const float iv0 = inv[r0];
        const float iv1 = inv[r1];
#pragma unroll
        for (int ni = 0; ni < 4; ni++) {
            const int cc = colBase + warp_n * 32 + ni * 8 + qt * 2;
            const float* a4 = acc[mi][ni];
            *reinterpret_cast<float2*>(C + (size_t)r0 * Cld + cc) =
                make_float2(a4[0] * iv0, a4[1] * iv0);
            *reinterpret_cast<float2*>(C + (size_t)r1 * Cld + cc) =
                make_float2(a4[2] * iv1, a4[3] * iv1);
        }
    }
}

// ---------------------------------------------------------------------------
// prep: per-row normalize Wh -> fp16. One warp per row.
// ---------------------------------------------------------------------------
__global__ void prep_norm_f16(const float* __restrict__ Wh, __half* __restrict__ A)
{
    int row  = blockIdx.x * 8 + (threadIdx.x >> 5);
    int lane = threadIdx.x & 31;
    const float4* r4 = reinterpret_cast<const float4*>(Wh + (size_t)row * DD);

    float4 v[4];
    float ss = 0.f;
#pragma unroll
    for (int i = 0; i < 4; i++) {
        v[i] = r4[lane + i * 32];
        ss = fmaf(v[i].x, v[i].x, ss); ss = fmaf(v[i].y, v[i].y, ss);
        ss = fmaf(v[i].z, v[i].z, ss); ss = fmaf(v[i].w, v[i].w, ss);
    }
#pragma unroll
    for (int off = 16; off > 0; off >>= 1) ss += __shfl_xor_sync(0xffffffffu, ss, off);
    float s = rsqrtf(ss + EPSF);

    __half* pa = A + (size_t)row * DD;
#pragma unroll
    for (int i = 0; i < 4; i++) {
        int col = (lane + i * 32) * 4;
        *reinterpret_cast<__half2*>(pa + col)     = __floats2half2_rn(v[i].x * s, v[i].y * s);
        *reinterpret_cast<__half2*>(pa + col + 2) = __floats2half2_rn(v[i].z * s, v[i].w * s);
    }
}

// ---------------------------------------------------------------------------
// tsplit: Bt[d][n] = fp16 split of Wh[n][d] — tiled transpose.
// ---------------------------------------------------------------------------
__global__ void tsplit_f16(const float* __restrict__ Wh,
                           __half* __restrict__ th, __half* __restrict__ tl)
{
    __shared__ float t[32][33];
    int bx = blockIdx.x, by = blockIdx.y;
    int tx = threadIdx.x, ty = threadIdx.y;
#pragma unroll
    for (int i = 0; i < 32; i += 8)
        t[ty + i][tx] = Wh[(size_t)(by * 32 + ty + i) * DD + bx * 32 + tx];
    __syncthreads();
#pragma unroll
    for (int i = 0; i < 32; i += 8) {
        float x = t[tx][ty + i];
        __half h = __float2half_rn(x);
        __half l = __float2half_rn(x - __half2float(h));
        size_t o = (size_t)(bx * 32 + ty + i) * NN + by * 32 + tx;
        th[o] = h; tl[o] = l;
    }
}

// ---------------------------------------------------------------------------
// rowsum: inv[row] = 1 / sum(P[row, :])   (fp32 accumulate over fp16 P)
// ---------------------------------------------------------------------------
__global__ void rowsum_inv(const __half* __restrict__ P, float* __restrict__ inv)
{
    __shared__ float red[256];
    const size_t row = blockIdx.x;
    const __half2* p2 = reinterpret_cast<const __half2*>(P + row * (size_t)NN);
    const int tid = threadIdx.x;

    float s = 0.f;
    for (int i = tid; i < NN / 2; i += 256) {
        float2 v = __half22float2(p2[i]);
        s += v.x + v.y;
    }
    red[tid] = s; __syncthreads();
    for (int st = 128; st > 0; st >>= 1) {
        if (tid < st) red[tid] += red[tid + st];
        __syncthreads();
    }
    if (tid == 0) inv[row] = 1.0f / red[0];
}

// ---------------------------------------------------------------------------
extern "C" void kernel_launch(void* const* d_in, const int* in_sizes, int n_in,
                              void* d_out, int out_size)
{
    const float* h   = (const float*)d_in[0];   // [8192, 512]
    const int*   adj = (const int*)d_in[1];     // [8192, 8192]
    const float* W   = (const float*)d_in[2];   // [512, 512]
    float* out = (float*)d_out;                 // [8192, 512]

    void* p;
    cudaGetSymbolAddress(&p, g_Wh);  float*  Wh  = (float*)p;
    cudaGetSymbolAddress(&p, g_hh);  __half* hh  = (__half*)p;
    cudaGetSymbolAddress(&p, g_hl);  __half* hl  = (__half*)p;
    cudaGetSymbolAddress(&p, g_wsh); __half* wsh = (__half*)p;
    cudaGetSymbolAddress(&p, g_wsl); __half* wsl = (__half*)p;
    cudaGetSymbolAddress(&p, g_An);  __half* An  = (__half*)p;
    cudaGetSymbolAddress(&p, g_Bth); __half* Bth = (__half*)p;
    cudaGetSymbolAddress(&p, g_Btl); __half* Btl = (__half*)p;
    cudaGetSymbolAddress(&p, g_p);   __half* P   = (__half*)p;
    cudaGetSymbolAddress(&p, g_inv); float*  inv = (float*)p;

    const int SMEM = 98304;
    cudaFuncSetAttribute((const void*)hmma3h,
                         cudaFuncAttributeMaxDynamicSharedMemorySize, SMEM);
    cudaFuncSetAttribute((const void*)hmma_sim,
                         cudaFuncAttributeMaxDynamicSharedMemorySize, SMEM);
    cudaFuncSetAttribute((const void*)hmma_av,
                         cudaFuncAttributeMaxDynamicSharedMemorySize, SMEM);

    // 1) fp16 splits of h and W
    split_hl<<<(NN * DD + 255) / 256, 256>>>(h, hh, hl, NN * DD);
    split_hl<<<(DD * DD + 255) / 256, 256>>>(W, wsh, wsl, DD * DD);
    // 2) Wh = h @ W^T via 3-term fp16 HMMA (fp32 out)
    hmma3h<<<dim3(DD / 128, NN / 128), 256, SMEM>>>(hh, hl, wsh, wsl, Wh, DD, DD);
    // 3) normalized rows -> fp16
    prep_norm_f16<<<NN / 8, 256>>>(Wh, An);
    // 4) Wh^T fp16 splits (B of AV GEMM)
    tsplit_f16<<<dim3(DD / 32, NN / 32), dim3(32, 8)>>>(Wh, Bth, Btl);
    // 5) P = exp(sim - 1) masked  (single-term fp16 HMMA; no row max needed)
    hmma_sim<<<dim3(NN / 128, NN / 128), 256, SMEM>>>(An, P, DD, adj);
    // 6) inv row sums
    rowsum_inv<<<NN, 256>>>(P, inv);
    // 7) out = (P @ Wh) * inv  (2-term fp16 HMMA, K = 8192)
    hmma_av<<<dim3(DD / 128, NN / 128), 256, SMEM>>>(P, Bth, Btl, out, NN, DD, inv);
}

// round 12
// speedup vs baseline: 6.4454x; 1.4552x over previous
#include <cuda_runtime.h>
#include <cuda_fp16.h>
#include <math.h>
#include <stdint.h>

#define NN 8192
#define DD 512
#define EPSF 1e-8f

// ---------------- scratch (__device__ globals; no allocation) ----------------
__device__ float  g_Wh [(size_t)NN * DD];          // fp32 Wh
__device__ __half g_hh [(size_t)NN * DD];          // h splits
__device__ __half g_hl [(size_t)NN * DD];
__device__ __half g_wsh[(size_t)DD * DD];          // W splits
__device__ __half g_wsl[(size_t)DD * DD];
__device__ __half g_An [(size_t)NN * DD];          // normalized Wh (fp16)
__device__ __half g_Vt [(size_t)DD * NN];          // Wh^T (fp16)
__device__ __half g_p  [(size_t)NN * NN];          // p = exp(sim-1) masked (134MB)
__device__ float  g_inv[NN];                       // 1 / row sum

// ---------------- PTX helpers (baseline PTX, sm_80+) ------------------------
__device__ __forceinline__ uint32_t smem_u32(const void* p) {
    uint32_t a;
    asm("{ .reg .u64 t; cvta.to.shared.u64 t, %1; cvt.u32.u64 %0, t; }"
        : "=r"(a) : "l"(p));
    return a;
}
__device__ __forceinline__ void cpasync16(uint32_t dst, const void* src) {
    asm volatile("cp.async.cg.shared.global [%0], [%1], 16;"
                 :: "r"(dst), "l"(src) : "memory");
}
__device__ __forceinline__ void cp_commit() {
    asm volatile("cp.async.commit_group;" ::: "memory");
}
__device__ __forceinline__ void ldsm4(uint32_t* r, uint32_t addr) {
    asm volatile("ldmatrix.sync.aligned.m8n8.x4.shared.b16 {%0,%1,%2,%3}, [%4];"
                 : "=r"(r[0]), "=r"(r[1]), "=r"(r[2]), "=r"(r[3]) : "r"(addr));
}
__device__ __forceinline__ void mma16816h(float* d, const uint32_t* a, const uint32_t* b) {
    asm volatile(
        "mma.sync.aligned.m16n8k16.row.col.f32.f16.f16.f32 "
        "{%0,%1,%2,%3}, {%4,%5,%6,%7}, {%8,%9}, {%0,%1,%2,%3};"
        : "+f"(d[0]), "+f"(d[1]), "+f"(d[2]), "+f"(d[3])
        : "r"(a[0]), "r"(a[1]), "r"(a[2]), "r"(a[3]), "r"(b[0]), "r"(b[1]));
}

// swizzled offset in a [rows x 32 f16] tile (64B pitch, 16B units)
__device__ __forceinline__ uint32_t swz64(int row, int u) {
    return (uint32_t)(row * 64 + ((u ^ ((row >> 1) & 3)) << 4));
}
// swizzled offset in a [rows x 64 f16] tile (128B pitch, 16B units)
__device__ __forceinline__ uint32_t swz128(int row, int u) {
    return (uint32_t)(row * 128 + ((u ^ (row & 7)) << 4));
}

// ---------------------------------------------------------------------------
// split: x -> fp16 hi + fp16 lo
// ---------------------------------------------------------------------------
__global__ void split_hl(const float* __restrict__ x, __half* __restrict__ hi,
                         __half* __restrict__ lo, int n)
{
    int i = blockIdx.x * blockDim.x + threadIdx.x;
    if (i < n) {
        float v = x[i];
        __half h = __float2half_rn(v);
        hi[i] = h;
        lo[i] = __float2half_rn(v - __half2float(h));
    }
}

// ---------------------------------------------------------------------------
// 3-term fp16-split GEMM (NT): C = (Ahi+Alo)@(Bhi+Blo)^T -> fp32 C.
// CTA 128x128, K-chunk 32, 3-stage pipeline. (Wh = h @ W^T)
// ---------------------------------------------------------------------------
__global__ __launch_bounds__(256, 2)
void hmma3h(const __half* __restrict__ Ahi, const __half* __restrict__ Alo,
            const __half* __restrict__ Bhi, const __half* __restrict__ Blo,
            float* __restrict__ C, int K, int Cld)
{
    extern __shared__ char smem[];
    const uint32_t base = smem_u32(smem);

    const int tid  = threadIdx.x;
    const int lane = tid & 31;
    const int wid  = tid >> 5;
    const int warp_m = wid & 1;
    const int warp_n = wid >> 1;
    const int rowBase = blockIdx.y * 128;
    const int colBase = blockIdx.x * 128;

    const __half* srcs[4] = { Ahi, Alo, Bhi, Blo };
    const int rb[4] = { rowBase, rowBase, colBase, colBase };

    float acc[4][4][4];
#pragma unroll
    for (int mi = 0; mi < 4; mi++)
#pragma unroll
        for (int ni = 0; ni < 4; ni++)
#pragma unroll
            for (int r = 0; r < 4; r++) acc[mi][ni][r] = 0.f;

    const int NC = K >> 5;

    auto prefetch = [&](int c, int stage) {
#pragma unroll
        for (int it = 0; it < 8; it++) {
            const int t   = it >> 1;
            const int rem = ((it & 1) << 8) + tid;
            const int row = rem >> 2;
            const int u   = rem & 3;
            const __half* sp =
                srcs[t] + (size_t)(rb[t] + row) * K + ((size_t)c << 5) + u * 8;
            uint32_t dst = base + (uint32_t)stage * 32768u + (uint32_t)t * 8192u
                         + swz64(row, u);
            cpasync16(dst, sp);
        }
        cp_commit();
    };

    prefetch(0, 0);
    prefetch(1, 1);

    for (int c = 0; c < NC; c++) {
        if (c + 1 < NC) asm volatile("cp.async.wait_group 1;" ::: "memory");
        else            asm volatile("cp.async.wait_group 0;" ::: "memory");
        __syncthreads();
        if (c + 2 < NC) prefetch(c + 2, (c + 2) % 3);

        const uint32_t st   = base + (uint32_t)(c % 3) * 32768u;
        const uint32_t tAhi = st;
        const uint32_t tAlo = st + 8192u;
        const uint32_t tBhi = st + 16384u;
        const uint32_t tBlo = st + 24576u;
        const int lrow = lane & 15;

#pragma unroll
        for (int ks = 0; ks < 2; ks++) {
            const int lu = ks * 2 + (lane >> 4);
            uint32_t ah[4][4], bh[4][2], bl[4][2];
#pragma unroll
            for (int mi = 0; mi < 4; mi++)
                ldsm4(ah[mi], tAhi + swz64(warp_m * 64 + mi * 16 + lrow, lu));
#pragma unroll
            for (int g = 0; g < 2; g++) {
                uint32_t r[4];
                ldsm4(r, tBhi + swz64(warp_n * 32 + g * 16 + lrow, lu));
                bh[g * 2 + 0][0] = r[0]; bh[g * 2 + 1][0] = r[1];
                bh[g * 2 + 0][1] = r[2]; bh[g * 2 + 1][1] = r[3];
                ldsm4(r, tBlo + swz64(warp_n * 32 + g * 16 + lrow, lu));
                bl[g * 2 + 0][0] = r[0]; bl[g * 2 + 1][0] = r[1];
                bl[g * 2 + 0][1] = r[2]; bl[g * 2 + 1][1] = r[3];
            }
#pragma unroll
            for (int mi = 0; mi < 4; mi++)
#pragma unroll
                for (int ni = 0; ni < 4; ni++) {
                    mma16816h(acc[mi][ni], ah[mi], bh[ni]);
                    mma16816h(acc[mi][ni], ah[mi], bl[ni]);
                }
            uint32_t al[4][4];
#pragma unroll
            for (int mi = 0; mi < 4; mi++)
                ldsm4(al[mi], tAlo + swz64(warp_m * 64 + mi * 16 + lrow, lu));
#pragma unroll
            for (int mi = 0; mi < 4; mi++)
#pragma unroll
                for (int ni = 0; ni < 4; ni++)
                    mma16816h(acc[mi][ni], al[mi], bh[ni]);
        }
    }

    const int quad = lane >> 2;
    const int qt   = lane & 3;
#pragma unroll
    for (int mi = 0; mi < 4; mi++) {
#pragma unroll
        for (int ni = 0; ni < 4; ni++) {
            const int r0 = rowBase + warp_m * 64 + mi * 16 + quad;
            const int r1 = r0 + 8;
            const int cc = colBase + warp_n * 32 + ni * 8 + qt * 2;
            const float* a4 = acc[mi][ni];
            *reinterpret_cast<float2*>(C + (size_t)r0 * Cld + cc) =
                make_float2(a4[0], a4[1]);
            *reinterpret_cast<float2*>(C + (size_t)r1 * Cld + cc) =
                make_float2(a4[2], a4[3]);
        }
    }
}

// ---------------------------------------------------------------------------
// SIM GEMM: sim = An @ An^T (single fp16 term), epilogue:
//   p = (adj>0 || diag) ? exp(sim - 1) : 0   -> fp16 P.
// CTA 128x128, K-chunk 64, 3-stage pipeline.
// ---------------------------------------------------------------------------
__global__ __launch_bounds__(256, 2)
void hmma_sim(const __half* __restrict__ A, __half* __restrict__ P,
              int K, const int* __restrict__ adj)
{
    extern __shared__ char smem[];
    const uint32_t base = smem_u32(smem);

    const int tid  = threadIdx.x;
    const int lane = tid & 31;
    const int wid  = tid >> 5;
    const int warp_m = wid & 1;
    const int warp_n = wid >> 1;
    const int rowBase = blockIdx.y * 128;
    const int colBase = blockIdx.x * 128;

    float acc[4][4][4];
#pragma unroll
    for (int mi = 0; mi < 4; mi++)
#pragma unroll
        for (int ni = 0; ni < 4; ni++)
#pragma unroll
            for (int r = 0; r < 4; r++) acc[mi][ni][r] = 0.f;

    const int NC = K >> 6;

    auto prefetch = [&](int c, int stage) {
#pragma unroll
        for (int it = 0; it < 8; it++) {
            const int t   = it >> 2;
            const int rem = ((it & 3) << 8) + tid;
            const int row = rem >> 3;
            const int u   = rem & 7;
            const __half* sp = A + (size_t)((t ? colBase : rowBase) + row) * K
                             + ((size_t)c << 6) + u * 8;
            uint32_t dst = base + (uint32_t)stage * 32768u + (uint32_t)t * 16384u
                         + swz128(row, u);
            cpasync16(dst, sp);
        }
        cp_commit();
    };

    prefetch(0, 0);
    prefetch(1, 1);

    for (int c = 0; c < NC; c++) {
        if (c + 1 < NC) asm volatile("cp.async.wait_group 1;" ::: "memory");
        else            asm volatile("cp.async.wait_group 0;" ::: "memory");
        __syncthreads();
        if (c + 2 < NC) prefetch(c + 2, (c + 2) % 3);

        const uint32_t sA = base + (uint32_t)(c % 3) * 32768u;
        const uint32_t sB = sA + 16384u;
        const int lrow = lane & 15;
#pragma unroll
        for (int ks = 0; ks < 4; ks++) {
            const int lu = ks * 2 + (lane >> 4);
            uint32_t ah[4][4], b[4][2];
#pragma unroll
            for (int mi = 0; mi < 4; mi++)
                ldsm4(ah[mi], sA + swz128(warp_m * 64 + mi * 16 + lrow, lu));
#pragma unroll
            for (int g = 0; g < 2; g++) {
                uint32_t t4[4];
                ldsm4(t4, sB + swz128(warp_n * 32 + g * 16 + lrow, lu));
                b[g * 2 + 0][0] = t4[0]; b[g * 2 + 1][0] = t4[1];
                b[g * 2 + 0][1] = t4[2]; b[g * 2 + 1][1] = t4[3];
            }
#pragma unroll
            for (int mi = 0; mi < 4; mi++)
#pragma unroll
                for (int ni = 0; ni < 4; ni++)
                    mma16816h(acc[mi][ni], ah[mi], b[ni]);
        }
    }

    // epilogue: mask + exp(sim - 1) -> fp16
    const int quad = lane >> 2;
    const int qt   = lane & 3;
#pragma unroll
    for (int mi = 0; mi < 4; mi++) {
#pragma unroll
        for (int ni = 0; ni < 4; ni++) {
            const int r0 = rowBase + warp_m * 64 + mi * 16 + quad;
            const int r1 = r0 + 8;
            const int cc = colBase + warp_n * 32 + ni * 8 + qt * 2;
            const float* a4 = acc[mi][ni];
            int2 m0 = *reinterpret_cast<const int2*>(adj + (size_t)r0 * NN + cc);
            int2 m1 = *reinterpret_cast<const int2*>(adj + (size_t)r1 * NN + cc);
            float p00 = (m0.x > 0 || r0 == cc)     ? __expf(a4[0] - 1.f) : 0.f;
            float p01 = (m0.y > 0 || r0 == cc + 1) ? __expf(a4[1] - 1.f) : 0.f;
            float p10 = (m1.x > 0 || r1 == cc)     ? __expf(a4[2] - 1.f) : 0.f;
            float p11 = (m1.y > 0 || r1 == cc + 1) ? __expf(a4[3] - 1.f) : 0.f;
            *reinterpret_cast<__half2*>(P + (size_t)r0 * NN + cc) =
                __floats2half2_rn(p00, p01);
            *reinterpret_cast<__half2*>(P + (size_t)r1 * NN + cc) =
                __floats2half2_rn(p10, p11);
        }
    }
}

// ---------------------------------------------------------------------------
// AV GEMM: out = (P @ V^T) * inv[row]. SINGLE fp16 term, fp32 accum.
// CTA 128x128, K-chunk 64, 3-stage pipeline (32KB/stage).
// ---------------------------------------------------------------------------
__global__ __launch_bounds__(256, 2)
void hmma_av(const __half* __restrict__ P, const __half* __restrict__ V,
             float* __restrict__ C, int K, int Cld, const float* __restrict__ inv)
{
    extern __shared__ char smem[];
    const uint32_t base = smem_u32(smem);

    const int tid  = threadIdx.x;
    const int lane = tid & 31;
    const int wid  = tid >> 5;
    const int warp_m = wid & 1;
    const int warp_n = wid >> 1;
    const int rowBase = blockIdx.y * 128;
    const int colBase = blockIdx.x * 128;

    float acc[4][4][4];
#pragma unroll
    for (int mi = 0; mi < 4; mi++)
#pragma unroll
        for (int ni = 0; ni < 4; ni++)
#pragma unroll
            for (int r = 0; r < 4; r++) acc[mi][ni][r] = 0.f;

    const int NC = K >> 6;

    auto prefetch = [&](int c, int stage) {
#pragma unroll
        for (int it = 0; it < 8; it++) {
            const int t   = it >> 2;                    // 0 = P, 1 = V
            const int rem = ((it & 3) << 8) + tid;
            const int row = rem >> 3;
            const int u   = rem & 7;
            const __half* sp = (t ? V + (size_t)(colBase + row) * K
                                  : P + (size_t)(rowBase + row) * K)
                             + ((size_t)c << 6) + u * 8;
            uint32_t dst = base + (uint32_t)stage * 32768u + (uint32_t)t * 16384u
                         + swz128(row, u);
            cpasync16(dst, sp);
        }
        cp_commit();
    };

    prefetch(0, 0);
    prefetch(1, 1);

    for (int c = 0; c < NC; c++) {
        if (c + 1 < NC) asm volatile("cp.async.wait_group 1;" ::: "memory");
        else            asm volatile("cp.async.wait_group 0;" ::: "memory");
        __syncthreads();
        if (c + 2 < NC) prefetch(c + 2, (c + 2) % 3);

        const uint32_t sP = base + (uint32_t)(c % 3) * 32768u;
        const uint32_t sV = sP + 16384u;
        const int lrow = lane & 15;
#pragma unroll
        for (int ks = 0; ks < 4; ks++) {
            const int lu = ks * 2 + (lane >> 4);
            uint32_t ap[4][4], b[4][2];
#pragma unroll
            for (int mi = 0; mi < 4; mi++)
                ldsm4(ap[mi], sP + swz128(warp_m * 64 + mi * 16 + lrow, lu));
#pragma unroll
            for (int g = 0; g < 2; g++) {
                uint32_t t4[4];
                ldsm4(t4, sV + swz128(warp_n * 32 + g * 16 + lrow, lu));
                b[g * 2 + 0][0] = t4[0]; b[g * 2 + 1][0] = t4[1];
                b[g * 2 + 0][1] = t4[2]; b[g * 2 + 1][1] = t4[3];
            }
#pragma unroll
            for (int mi = 0; mi < 4; mi++)
#pragma unroll
                for (int ni = 0; ni < 4; ni++)
                    mma16816h(acc[mi][ni], ap[mi], b[ni]);
        }
    }

    const int quad = lane >> 2;
    const int qt   = lane & 3;
#pragma unroll
    for (int mi = 0; mi < 4; mi++) {
        const int r0 = rowBase + warp_m * 64 + mi * 16 + quad;
        const int r1 = r0 + 8;
        const float iv0 = inv[r0];
        const float iv1 = inv[r1];
#pragma unroll
        for (int ni = 0; ni < 4; ni++) {
            const int cc = colBase + warp_n * 32 + ni * 8 + qt * 2;
            const float* a4 = acc[mi][ni];
            *reinterpret_cast<float2*>(C + (size_t)r0 * Cld + cc) =
                make_float2(a4[0] * iv0, a4[1] * iv0);
            *reinterpret_cast<float2*>(C + (size_t)r1 * Cld + cc) =
                make_float2(a4[2] * iv1, a4[3] * iv1);
        }
    }
}

// ---------------------------------------------------------------------------
// prep: per-row normalize Wh -> fp16. One warp per row.
// ---------------------------------------------------------------------------
__global__ void prep_norm_f16(const float* __restrict__ Wh, __half* __restrict__ A)
{
    int row  = blockIdx.x * 8 + (threadIdx.x >> 5);
    int lane = threadIdx.x & 31;
    const float4* r4 = reinterpret_cast<const float4*>(Wh + (size_t)row * DD);

    float4 v[4];
    float ss = 0.f;
#pragma unroll
    for (int i = 0; i < 4; i++) {
        v[i] = r4[lane + i * 32];
        ss = fmaf(v[i].x, v[i].x, ss); ss = fmaf(v[i].y, v[i].y, ss);
        ss = fmaf(v[i].z, v[i].z, ss); ss = fmaf(v[i].w, v[i].w, ss);
    }
#pragma unroll
    for (int off = 16; off > 0; off >>= 1) ss += __shfl_xor_sync(0xffffffffu, ss, off);
    float s = rsqrtf(ss + EPSF);

    __half* pa = A + (size_t)row * DD;
#pragma unroll
    for (int i = 0; i < 4; i++) {
        int col = (lane + i * 32) * 4;
        *reinterpret_cast<__half2*>(pa + col)     = __floats2half2_rn(v[i].x * s, v[i].y * s);
        *reinterpret_cast<__half2*>(pa + col + 2) = __floats2half2_rn(v[i].z * s, v[i].w * s);
    }
}

// ---------------------------------------------------------------------------
// transpose Wh -> fp16 V^T.
// ---------------------------------------------------------------------------
__global__ void t_f16(const float* __restrict__ Wh, __half* __restrict__ th)
{
    __shared__ float t[32][33];
    int bx = blockIdx.x, by = blockIdx.y;
    int tx = threadIdx.x, ty = threadIdx.y;
#pragma unroll
    for (int i = 0; i < 32; i += 8)
        t[ty + i][tx] = Wh[(size_t)(by * 32 + ty + i) * DD + bx * 32 + tx];
    __syncthreads();
#pragma unroll
    for (int i = 0; i < 32; i += 8) {
        size_t o = (size_t)(bx * 32 + ty + i) * NN + by * 32 + tx;
        th[o] = __float2half_rn(t[tx][ty + i]);
    }
}

// ---------------------------------------------------------------------------
// rowsum: inv[row] = 1 / sum(P[row, :])   (fp32 accumulate, uint4 loads)
// ---------------------------------------------------------------------------
__global__ void rowsum_inv(const __half* __restrict__ P, float* __restrict__ inv)
{
    __shared__ float red[256];
    const size_t row = blockIdx.x;
    const uint4* p4 = reinterpret_cast<const uint4*>(P + row * (size_t)NN);
    const int tid = threadIdx.x;

    float s = 0.f;
#pragma unroll
    for (int i = 0; i < NN / (8 * 256); i++) {
        uint4 v = p4[tid + i * 256];
        __half2 a = *reinterpret_cast<__half2*>(&v.x);
        __half2 b = *reinterpret_cast<__half2*>(&v.y);
        __half2 c = *reinterpret_cast<__half2*>(&v.z);
        __half2 d = *reinterpret_cast<__half2*>(&v.w);
        float2 fa = __half22float2(a), fb = __half22float2(b);
        float2 fc = __half22float2(c), fd = __half22float2(d);
        s += (fa.x + fa.y) + (fb.x + fb.y) + (fc.x + fc.y) + (fd.x + fd.y);
    }
    red[tid] = s; __syncthreads();
    for (int st = 128; st > 0; st >>= 1) {
        if (tid < st) red[tid] += red[tid + st];
        __syncthreads();
    }
    if (tid == 0) inv[row] = 1.0f / red[0];
}

// ---------------------------------------------------------------------------
extern "C" void kernel_launch(void* const* d_in, const int* in_sizes, int n_in,
                              void* d_out, int out_size)
{
    const float* h   = (const float*)d_in[0];   // [8192, 512]
    const int*   adj = (const int*)d_in[1];     // [8192, 8192]
    const float* W   = (const float*)d_in[2];   // [512, 512]
    float* out = (float*)d_out;                 // [8192, 512]

    void* p;
    cudaGetSymbolAddress(&p, g_Wh);  float*  Wh  = (float*)p;
    cudaGetSymbolAddress(&p, g_hh);  __half* hh  = (__half*)p;
    cudaGetSymbolAddress(&p, g_hl);  __half* hl  = (__half*)p;
    cudaGetSymbolAddress(&p, g_wsh); __half* wsh = (__half*)p;
    cudaGetSymbolAddress(&p, g_wsl); __half* wsl = (__half*)p;
    cudaGetSymbolAddress(&p, g_An);  __half* An  = (__half*)p;
    cudaGetSymbolAddress(&p, g_Vt);  __half* Vt  = (__half*)p;
    cudaGetSymbolAddress(&p, g_p);   __half* P   = (__half*)p;
    cudaGetSymbolAddress(&p, g_inv); float*  inv = (float*)p;

    const int SMEM = 98304;
    cudaFuncSetAttribute((const void*)hmma3h,
                         cudaFuncAttributeMaxDynamicSharedMemorySize, SMEM);
    cudaFuncSetAttribute((const void*)hmma_sim,
                         cudaFuncAttributeMaxDynamicSharedMemorySize, SMEM);
    cudaFuncSetAttribute((const void*)hmma_av,
                         cudaFuncAttributeMaxDynamicSharedMemorySize, SMEM);

    // 1) fp16 splits of h and W
    split_hl<<<(NN * DD + 255) / 256, 256>>>(h, hh, hl, NN * DD);
    split_hl<<<(DD * DD + 255) / 256, 256>>>(W, wsh, wsl, DD * DD);
    // 2) Wh = h @ W^T via 3-term fp16 HMMA (fp32 out)
    hmma3h<<<dim3(DD / 128, NN / 128), 256, SMEM>>>(hh, hl, wsh, wsl, Wh, DD, DD);
    // 3) normalized rows -> fp16
    prep_norm_f16<<<NN / 8, 256>>>(Wh, An);
    // 4) Wh^T -> fp16 (V of AV GEMM)
    t_f16<<<dim3(DD / 32, NN / 32), dim3(32, 8)>>>(Wh, Vt);
    // 5) P = exp(sim - 1) masked  (single-term fp16 HMMA; no row max needed)
    hmma_sim<<<dim3(NN / 128, NN / 128), 256, SMEM>>>(An, P, DD, adj);
    // 6) inv row sums
    rowsum_inv<<<NN, 256>>>(P, inv);
    // 7) out = (P @ V^T) * inv  (single-term fp16 HMMA, K = 8192)
    hmma_av<<<dim3(DD / 128, NN / 128), 256, SMEM>>>(P, Vt, out, NN, DD, inv);
}